// round 11
// baseline (speedup 1.0000x reference)
#include <cuda_runtime.h>
#include <cuda_fp16.h>
#include <cstdint>

#define NUM_HEADS 8
#define D_MODEL   512
#define DK        64
#define SEQ       2048
#define BATCH     4
#define MT        (BATCH * SEQ)        // 8192
#define BH        (BATCH * NUM_HEADS)  // 32

// ============================================================================
// Scratch (device globals — no allocation allowed)
// ============================================================================
__device__ __align__(16) __half g_Ah[3 * MT * D_MODEL];
__device__ __align__(16) __half g_Al[3 * MT * D_MODEL];
__device__ __align__(16) __half g_Wth[4 * D_MODEL * D_MODEL];
__device__ __align__(16) __half g_Wtl[4 * D_MODEL * D_MODEL];
__device__ __align__(16) __half g_Qh[BH * SEQ * DK];
__device__ __align__(16) __half g_Ql[BH * SEQ * DK];
__device__ __align__(16) __half g_Kh[BH * SEQ * DK];
__device__ __align__(16) __half g_Kl[BH * SEQ * DK];
__device__ __align__(16) __half g_Khc[BH * SEQ * DK];  // compacted K hi
__device__ __align__(16) __half g_Klc[BH * SEQ * DK];  // compacted K lo
__device__ __align__(16) float  g_Vf[BH * SEQ * DK];
__device__ __align__(16) __half g_Vth[BH * DK * SEQ];  // compacted V^T hi
__device__ __align__(16) __half g_Vtl[BH * DK * SEQ];  // compacted V^T lo
__device__ int g_idx[BATCH * SEQ];
__device__ int g_nk[BATCH];

// 0.125 (1/sqrt(d_k)) * log2(e): folded into Q projection so S is in log2 units
#define QSCALE 0.18033688011117128f

// ============================================================================
// PTX primitives (all legal at compute_103 baseline)
// ============================================================================
__device__ __forceinline__ uint32_t smem_to_u32(const void* p) {
    uint32_t a;
    asm("{ .reg .u64 t; cvta.to.shared.u64 t, %1; cvt.u32.u64 %0, t; }"
        : "=r"(a) : "l"(p));
    return a;
}

__device__ __forceinline__ void ldsm4(uint32_t* r, uint32_t addr) {
    asm volatile("ldmatrix.sync.aligned.m8n8.x4.shared.b16 {%0,%1,%2,%3}, [%4];"
                 : "=r"(r[0]), "=r"(r[1]), "=r"(r[2]), "=r"(r[3]) : "r"(addr));
}

// f16 inputs, f32 accumulate (main pass)
__device__ __forceinline__ void mma_f32h(float* c, const uint32_t* a,
                                         const uint32_t* b) {
    asm volatile(
        "mma.sync.aligned.m16n8k16.row.col.f32.f16.f16.f32 "
        "{%0,%1,%2,%3}, {%4,%5,%6,%7}, {%8,%9}, {%0,%1,%2,%3};"
        : "+f"(c[0]), "+f"(c[1]), "+f"(c[2]), "+f"(c[3])
        : "r"(a[0]), "r"(a[1]), "r"(a[2]), "r"(a[3]), "r"(b[0]), "r"(b[1]));
}

// f16 inputs, f16 accumulate (correction passes — 2x pipe rate)
__device__ __forceinline__ void mma_f16a(uint32_t* c, const uint32_t* a,
                                         const uint32_t* b) {
    asm volatile(
        "mma.sync.aligned.m16n8k16.row.col.f16.f16.f16.f16 "
        "{%0,%1}, {%2,%3,%4,%5}, {%6,%7}, {%0,%1};"
        : "+r"(c[0]), "+r"(c[1])
        : "r"(a[0]), "r"(a[1]), "r"(a[2]), "r"(a[3]), "r"(b[0]), "r"(b[1]));
}

__device__ __forceinline__ float2 h2f2(uint32_t u) {
    __half2 h = *reinterpret_cast<__half2*>(&u);
    return __half22float2(h);
}

#define CP16(dst, src) \
    asm volatile("cp.async.cg.shared.global [%0], [%1], 16;" \
                 :: "r"(dst), "l"(src) : "memory")
#define CP_COMMIT() asm volatile("cp.async.commit_group;" ::: "memory")
#define CP_WAIT0()  asm volatile("cp.async.wait_group 0;" ::: "memory")

// exp2 via magic-constant round + degree-4 poly on [-0.5, 0.5]; t <= 0.
__device__ __forceinline__ float fexp2m(float t) {
    t = fmaxf(t, -126.0f);
    float z = t + 12582912.0f;
    float f = t - (z - 12582912.0f);
    float p = fmaf(f, 0.0096181291f, 0.0555041087f);
    p = fmaf(p, f, 0.2402265069f);
    p = fmaf(p, f, 0.6931471806f);
    p = fmaf(p, f, 1.0f);
    uint32_t sb = (uint32_t)((__float_as_int(z) + 127) << 23);
    return __int_as_float(sb) * p;
}

// ============================================================================
// Mask prefix scan: per batch, build compacted index list + count
// ============================================================================
__global__ __launch_bounds__(1024) void mask_scan_kernel(
    const int* __restrict__ mask, int* __restrict__ idx, int* __restrict__ nk) {
    const int b = blockIdx.x, tid = threadIdx.x;
    const int lane = tid & 31, w = tid >> 5;
    const int* mp = mask + b * SEQ;
    int e0 = (mp[2 * tid] != 0), e1 = (mp[2 * tid + 1] != 0);
    int tsum = e0 + e1;
    int v = tsum;
#pragma unroll
    for (int o = 1; o < 32; o <<= 1) {
        int u = __shfl_up_sync(0xffffffffu, v, o);
        if (lane >= o) v += u;
    }
    __shared__ int ws[32];
    if (lane == 31) ws[w] = v;
    __syncthreads();
    if (w == 0) {
        int x = ws[lane];
#pragma unroll
        for (int o = 1; o < 32; o <<= 1) {
            int u = __shfl_up_sync(0xffffffffu, x, o);
            if (lane >= o) x += u;
        }
        ws[lane] = x;
    }
    __syncthreads();
    int base = ((w > 0) ? ws[w - 1] : 0) + (v - tsum);
    if (e0) idx[b * SEQ + base] = 2 * tid;
    if (e1) idx[b * SEQ + base + e0] = 2 * tid + 1;
    if (tid == 0) nk[b] = ws[31];
}

// ============================================================================
// KV gather: pack unmasked K rows (hi/lo) densely; gather+transpose+split V.
// ============================================================================
__global__ __launch_bounds__(256) void kv_gather_kernel(
    const __half* __restrict__ Kh, const __half* __restrict__ Kl,
    const float* __restrict__ Vf, const int* __restrict__ idx,
    const int* __restrict__ nk,
    __half* __restrict__ Khc, __half* __restrict__ Klc,
    __half* __restrict__ Vth, __half* __restrict__ Vtl) {
    const int t = blockIdx.x, bh = blockIdx.y, b = bh >> 3;
    const int tid = threadIdx.x;
    const int n = nk[b];
    const int j0 = t * 64;
    if (j0 >= ((n + 63) & ~63)) return;
    const int* idxb = idx + b * SEQ;

    const uint4 z4 = make_uint4(0, 0, 0, 0);
#pragma unroll
    for (int t2 = 0; t2 < 2; t2++) {
        int i = tid + t2 * 256;
        int r = i >> 3, j = i & 7;
        int jj = j0 + r;
        int row = (jj < n) ? idxb[jj] : -1;
        size_t src = ((size_t)bh * SEQ + row) * DK + j * 8;
        size_t dst = ((size_t)bh * SEQ + jj) * DK + j * 8;
        *(uint4*)(Khc + dst) = (row >= 0) ? *(const uint4*)(Kh + src) : z4;
        *(uint4*)(Klc + dst) = (row >= 0) ? *(const uint4*)(Kl + src) : z4;
    }

    __shared__ float ts[64][65];
    for (int i = tid; i < 4096; i += 256) {
        int r = i >> 6, c = i & 63;
        int jj = j0 + r;
        int row = (jj < n) ? idxb[jj] : -1;
        ts[r][c] = (row >= 0) ? Vf[((size_t)bh * SEQ + row) * DK + c] : 0.0f;
    }
    __syncthreads();
    for (int i = tid; i < 4096; i += 256) {
        int d = i >> 6, c = i & 63;
        float v = ts[c][d];
        __half hv = __float2half_rn(v);
        size_t o = ((size_t)bh * DK + d) * SEQ + j0 + c;
        Vth[o] = hv;
        Vtl[o] = __float2half_rn(v - __half2float(hv));
    }
}

// ============================================================================
// Prep kernels (batched over z)
// ============================================================================
__global__ void split_b_kernel(const float4* __restrict__ q,
                               const float4* __restrict__ k,
                               const float4* __restrict__ v,
                               __half* __restrict__ Ah,
                               __half* __restrict__ Al, int n4) {
    int i = blockIdx.x * blockDim.x + threadIdx.x;
    if (i >= n4) return;
    int z = blockIdx.y;
    const float4* in = (z == 0) ? q : (z == 1) ? k : v;
    __half2* hi = (__half2*)(Ah + (size_t)z * MT * D_MODEL);
    __half2* lo = (__half2*)(Al + (size_t)z * MT * D_MODEL);
    float4 vv = in[i];
    __half2 h01 = __floats2half2_rn(vv.x, vv.y);
    __half2 h23 = __floats2half2_rn(vv.z, vv.w);
    hi[2 * i]     = h01;
    hi[2 * i + 1] = h23;
    float2 f01 = __half22float2(h01), f23 = __half22float2(h23);
    lo[2 * i]     = __floats2half2_rn(vv.x - f01.x, vv.y - f01.y);
    lo[2 * i + 1] = __floats2half2_rn(vv.z - f23.x, vv.w - f23.y);
}

__global__ void wt_split_b_kernel(const float* __restrict__ W0,
                                  const float* __restrict__ W1,
                                  const float* __restrict__ W2,
                                  const float* __restrict__ W3,
                                  __half* __restrict__ Wth,
                                  __half* __restrict__ Wtl) {
    __shared__ float ts[32][33];
    int z = blockIdx.z;
    const float* W = (z == 0) ? W0 : (z == 1) ? W1 : (z == 2) ? W2 : W3;
    __half* oh = Wth + (size_t)z * D_MODEL * D_MODEL;
    __half* ol = Wtl + (size_t)z * D_MODEL * D_MODEL;
    int n0 = blockIdx.x * 32, k0 = blockIdx.y * 32;
    ts[threadIdx.y][threadIdx.x] = W[(size_t)(k0 + threadIdx.y) * 512 + n0 + threadIdx.x];
    __syncthreads();
    int n = n0 + threadIdx.y, k = k0 + threadIdx.x;
    float v = ts[threadIdx.x][threadIdx.y];
    __half hv = __float2half_rn(v);
    oh[(size_t)n * 512 + k] = hv;
    ol[(size_t)n * 512 + k] = __float2half_rn(v - __half2float(hv));
}

// ============================================================================
// HMMA GEMM (cp.async double-buffered), f16x3:
//   pass 1: Ah*Bh -> f32 accum;  passes 2,3: Al*Bh, Ah*Bl -> f16 accum (2x rate)
// z: 0=Q (pre-scaled by QSCALE, half hi/lo head-split), 1=K (half hi/lo),
// 2=V (f32 head-split), 3=out proj (f32 row-major to d_out).
// ============================================================================
#define GRB    80      // smem row bytes (40 halves)
#define GTILE  10240   // 128 rows
#define GSTAGE 40960   // 4 tiles
#define G_SMEM (2 * GSTAGE)

__global__ __launch_bounds__(256) void mm_gemm(
    const __half* __restrict__ Ahb, const __half* __restrict__ Alb,
    const __half* __restrict__ Wthb, const __half* __restrict__ Wtlb,
    const float* __restrict__ bq, const float* __restrict__ bk,
    const float* __restrict__ bv, const float* __restrict__ bo,
    __half* __restrict__ Qh, __half* __restrict__ Ql,
    __half* __restrict__ Kh, __half* __restrict__ Kl,
    float* __restrict__ Vf, float* __restrict__ dout, int zofs) {
    extern __shared__ __align__(16) char smg[];
    const int tid = threadIdx.x, wid = tid >> 5, lane = tid & 31;
    const int wm = wid >> 1, wn = wid & 1;
    const int gr = lane >> 2, gc = lane & 3;
    const int m0 = blockIdx.y * 128, n0 = blockIdx.x * 128;
    const int z = blockIdx.z + zofs;

    const __half* Ah = Ahb + (size_t)((z == 3) ? 0 : z) * MT * D_MODEL;
    const __half* Al = Alb + (size_t)((z == 3) ? 0 : z) * MT * D_MODEL;
    const __half* Bh = Wthb + (size_t)z * D_MODEL * D_MODEL;
    const __half* Bl = Wtlb + (size_t)z * D_MODEL * D_MODEL;
    const float* bias = (z == 0) ? bq : (z == 1) ? bk : (z == 2) ? bv : bo;

    const uint32_t sb = smem_to_u32(smg);
    const uint32_t rAh = (uint32_t)(wm * 32 + (lane & 15)) * GRB + (((lane >> 4) & 1) << 4);
    const uint32_t rBh = 2u * GTILE +
        (uint32_t)(wn * 64 + (lane & 7) + (((lane >> 4) & 1) << 3)) * GRB +
        (((lane >> 3) & 1) << 4);

    const int pr = tid >> 2, pj = tid & 3;
    const uint32_t poff = (uint32_t)pr * GRB + pj * 16;

    float c32[2][8][4];
    uint32_t c16[2][8][2];
#pragma unroll
    for (int i = 0; i < 2; i++)
#pragma unroll
        for (int j = 0; j < 8; j++) {
#pragma unroll
            for (int e = 0; e < 4; e++) c32[i][j][e] = 0.0f;
            c16[i][j][0] = 0u;
            c16[i][j][1] = 0u;
        }

    {
#pragma unroll
        for (int t = 0; t < 2; t++) {
            int r = pr + t * 64;
            uint32_t d = sb + poff + (uint32_t)t * 64 * GRB;
            size_t ga = (size_t)(m0 + r) * 512 + pj * 8;
            size_t gb = (size_t)(n0 + r) * 512 + pj * 8;
            CP16(d, Ah + ga);
            CP16(d + GTILE, Al + ga);
            CP16(d + 2 * GTILE, Bh + gb);
            CP16(d + 3 * GTILE, Bl + gb);
        }
        CP_COMMIT();
    }

    for (int kc = 0; kc < 16; kc++) {
        const uint32_t stg = sb + (uint32_t)(kc & 1) * GSTAGE;
        CP_WAIT0();
        __syncthreads();
        if (kc < 15) {
            const int k0 = (kc + 1) * 32;
            const uint32_t nstg = sb + (uint32_t)((kc + 1) & 1) * GSTAGE;
#pragma unroll
            for (int t = 0; t < 2; t++) {
                int r = pr + t * 64;
                uint32_t d = nstg + poff + (uint32_t)t * 64 * GRB;
                size_t ga = (size_t)(m0 + r) * 512 + k0 + pj * 8;
                size_t gb = (size_t)(n0 + r) * 512 + k0 + pj * 8;
                CP16(d, Ah + ga);
                CP16(d + GTILE, Al + ga);
                CP16(d + 2 * GTILE, Bh + gb);
                CP16(d + 3 * GTILE, Bl + gb);
            }
            CP_COMMIT();
        }

        const uint32_t aAh = stg + rAh, aBh = stg + rBh;
#pragma unroll
        for (int ks = 0; ks < 2; ks++) {
            uint32_t ah[2][4], al[2][4], bfr[4][4];
            ldsm4(ah[0], aAh + ks * 32);
            ldsm4(ah[1], aAh + 16 * GRB + ks * 32);
            ldsm4(al[0], aAh + GTILE + ks * 32);
            ldsm4(al[1], aAh + GTILE + 16 * GRB + ks * 32);
#pragma unroll
            for (int nt2 = 0; nt2 < 4; nt2++)
                ldsm4(bfr[nt2], aBh + nt2 * 16 * GRB + ks * 32);
            // pass 1: Ah*Bh -> f32 accum
#pragma unroll
            for (int nt2 = 0; nt2 < 4; nt2++)
#pragma unroll
                for (int q = 0; q < 2; q++)
#pragma unroll
                    for (int mt = 0; mt < 2; mt++)
                        mma_f32h(c32[mt][nt2 * 2 + q], ah[mt], &bfr[nt2][q * 2]);
            // pass 2: Al*Bh -> f16 accum
#pragma unroll
            for (int nt2 = 0; nt2 < 4; nt2++)
#pragma unroll
                for (int q = 0; q < 2; q++)
#pragma unroll
                    for (int mt = 0; mt < 2; mt++)
                        mma_f16a(c16[mt][nt2 * 2 + q], al[mt], &bfr[nt2][q * 2]);
            // reload B = Bl, pass 3: Ah*Bl -> f16 accum
#pragma unroll
            for (int nt2 = 0; nt2 < 4; nt2++)
                ldsm4(bfr[nt2], aBh + GTILE + nt2 * 16 * GRB + ks * 32);
#pragma unroll
            for (int nt2 = 0; nt2 < 4; nt2++)
#pragma unroll
                for (int q = 0; q < 2; q++)
#pragma unroll
                    for (int mt = 0; mt < 2; mt++)
                        mma_f16a(c16[mt][nt2 * 2 + q], ah[mt], &bfr[nt2][q * 2]);
        }
    }

    // Epilogue: merge f16 corrections, add bias, store
#pragma unroll
    for (int mt = 0; mt < 2; mt++) {
#pragma unroll
        for (int half_ = 0; half_ < 2; half_++) {
            int m = m0 + wm * 32 + mt * 16 + gr + half_ * 8;
            int bb = m >> 11, l = m & 2047;
#pragma unroll
            for (int nt = 0; nt < 8; nt++) {
                int n = n0 + wn * 64 + nt * 8 + 2 * gc;
                float2 cc = h2f2(c16[mt][nt][half_]);
                float v0 = c32[mt][nt][half_ * 2 + 0] + cc.x + bias[n];
                float v1 = c32[mt][nt][half_ * 2 + 1] + cc.y + bias[n + 1];
                if (z == 3) {
                    *(float2*)(dout + (size_t)m * 512 + n) = make_float2(v0, v1);
                } else if (z == 2) {
                    int h = n >> 6, d = n & 63;
                    *(float2*)(Vf + ((size_t)(bb * 8 + h) * SEQ + l) * DK + d) =
                        make_float2(v0, v1);
                } else {
                    if (z == 0) { v0 *= QSCALE; v1 *= QSCALE; }
                    int h = n >> 6, d = n & 63;
                    size_t o = ((size_t)(bb * 8 + h) * SEQ + l) * DK + d;
                    __half2 hh = __floats2half2_rn(v0, v1);
                    float2 hf = __half22float2(hh);
                    __half* oh = (z == 0) ? Qh : Kh;
                    __half* ol = (z == 0) ? Ql : Kl;
                    *(__half2*)(oh + o) = hh;
                    *(__half2*)(ol + o) = __floats2half2_rn(v0 - hf.x, v1 - hf.y);
                }
            }
        }
    }
}

// ============================================================================
// HMMA flash attention over compacted KV, f16x3 (main f32-acc + 2 f16-acc).
// 2 CTAs/SM; Q in smem; log2-domain scores; magic exp2; clamp masking.
// ============================================================================
#define ARB   144                 // smem row bytes (72 halves)
#define ATILE (256 * ARB)         // one stage: KH(64) KL(64) VH(64) VL(64)
#define QOFF  (2 * ATILE)         // Q region: QH(128) QL(128)
#define A_SMEM (2 * ATILE + 256 * ARB)   // 110592 bytes

__global__ __launch_bounds__(256, 2) void mm_attn(
    const __half* __restrict__ Qh, const __half* __restrict__ Ql,
    const __half* __restrict__ Kh, const __half* __restrict__ Kl,
    const __half* __restrict__ Vh, const __half* __restrict__ Vl,
    const int* __restrict__ nkp,
    __half* __restrict__ OutH, __half* __restrict__ OutL) {
    extern __shared__ __align__(16) char smA[];

    const int tid = threadIdx.x, wid = tid >> 5, lane = tid & 31;
    const int gr = lane >> 2, gc = lane & 3;
    const int q0 = blockIdx.x * 128;
    const int bh = blockIdx.y, b = bh >> 3, h = bh & 7;
    const int nk = nkp[b];
    const int niter = (nk + 63) >> 6;

    const __half* Qhp = Qh + (size_t)bh * SEQ * DK;
    const __half* Qlp = Ql + (size_t)bh * SEQ * DK;
    const __half* Khp = Kh + (size_t)bh * SEQ * DK;
    const __half* Klp = Kl + (size_t)bh * SEQ * DK;
    const __half* Vhp = Vh + (size_t)bh * DK * SEQ;
    const __half* Vlp = Vl + (size_t)bh * DK * SEQ;

    const uint32_t sb = smem_to_u32(smA);
    const int pr = tid >> 3, pj = tid & 7;

    // ---- prefetch KV tile 0 into stage 0
    if (niter > 0) {
#pragma unroll
        for (int t = 0; t < 2; t++) {
            int r = pr + t * 32;
            uint32_t d = sb + (uint32_t)r * ARB + pj * 16;
            size_t gk = (size_t)r * DK + pj * 8;
            size_t gv = (size_t)r * SEQ + pj * 8;
            CP16(d, Khp + gk);
            CP16(d + 64 * ARB, Klp + gk);
            CP16(d + 128 * ARB, Vhp + gv);
            CP16(d + 192 * ARB, Vlp + gv);
        }
        CP_COMMIT();
    }

    // ---- stage Q (persistent region)
#pragma unroll
    for (int t = 0; t < 4; t++) {
        int i = tid + t * 256;
        int r = i >> 3, j = i & 7;
        char* dsth = smA + QOFF + (size_t)r * ARB + j * 16;
        char* dstl = smA + QOFF + (size_t)(128 + r) * ARB + j * 16;
        *(uint4*)dsth = *(const uint4*)(Qhp + (size_t)(q0 + r) * DK + j * 8);
        *(uint4*)dstl = *(const uint4*)(Qlp + (size_t)(q0 + r) * DK + j * 8);
    }
    CP_WAIT0();
    __syncthreads();

    const uint32_t aQb = sb + QOFF +
        (uint32_t)(wid * 16 + (lane & 15)) * ARB + (((lane >> 4) & 1) << 4);
    const uint32_t bro = (uint32_t)((lane & 7) + (((lane >> 4) & 1) << 3)) * ARB +
                         (((lane >> 3) & 1) << 4);

    float m0_ = -1e30f, m1_ = -1e30f, l0_ = 0.0f, l1_ = 0.0f;
    float o[8][4];
#pragma unroll
    for (int j = 0; j < 8; j++)
#pragma unroll
        for (int e = 0; e < 4; e++) o[j][e] = 0.0f;

    for (int it = 0; it < niter; it++) {
        const int cur = it & 1;
        const uint32_t stg = sb + (uint32_t)cur * ATILE;
        const int kt = it * 64;

        if (it + 1 < niter) {
            const int ktn = kt + 64;
            const uint32_t nstg = sb + (uint32_t)(1 - cur) * ATILE;
#pragma unroll
            for (int t = 0; t < 2; t++) {
                int r = pr + t * 32;
                uint32_t d = nstg + (uint32_t)r * ARB + pj * 16;
                size_t gk = (size_t)(ktn + r) * DK + pj * 8;
                size_t gv = (size_t)r * SEQ + ktn + pj * 8;
                CP16(d, Khp + gk);
                CP16(d + 64 * ARB, Klp + gk);
                CP16(d + 128 * ARB, Vhp + gv);
                CP16(d + 192 * ARB, Vlp + gv);
            }
            CP_COMMIT();
        }

        // ---- S = Q @ K^T (f16x3: f32-acc main + f16-acc corrections)
        float s32[8][4];
        uint32_t s16[8][2];
#pragma unroll
        for (int j = 0; j < 8; j++) {
#pragma unroll
            for (int e = 0; e < 4; e++) s32[j][e] = 0.0f;
            s16[j][0] = 0u;
            s16[j][1] = 0u;
        }
        const uint32_t aKh = stg + bro, aKl = stg + 64 * ARB + bro;
#pragma unroll
        for (int ks = 0; ks < 4; ks++) {
            uint32_t qhf[4], qlf[4], kf[4][4];
            ldsm4(qhf, aQb + ks * 32);
            ldsm4(qlf, aQb + 128 * ARB + ks * 32);
#pragma unroll
            for (int nt2 = 0; nt2 < 4; nt2++)
                ldsm4(kf[nt2], aKh + nt2 * 16 * ARB + ks * 32);
#pragma unroll
            for (int nt2 = 0; nt2 < 4; nt2++)
#pragma unroll
                for (int q = 0; q < 2; q++)
                    mma_f32h(s32[nt2 * 2 + q], qhf, &kf[nt2][q * 2]);
#pragma unroll
            for (int nt2 = 0; nt2 < 4; nt2++)
#pragma unroll
                for (int q = 0; q < 2; q++)
                    mma_f16a(s16[nt2 * 2 + q], qlf, &kf[nt2][q * 2]);
#pragma unroll
            for (int nt2 = 0; nt2 < 4; nt2++)
                ldsm4(kf[nt2], aKl + nt2 * 16 * ARB + ks * 32);
#pragma unroll
            for (int nt2 = 0; nt2 < 4; nt2++)
#pragma unroll
                for (int q = 0; q < 2; q++)
                    mma_f16a(s16[nt2 * 2 + q], qhf, &kf[nt2][q * 2]);
        }

        // ---- merge corrections
        float s[8][4];
#pragma unroll
        for (int nt = 0; nt < 8; nt++) {
            float2 c01 = h2f2(s16[nt][0]);
            float2 c23 = h2f2(s16[nt][1]);
            s[nt][0] = s32[nt][0] + c01.x;
            s[nt][1] = s32[nt][1] + c01.y;
            s[nt][2] = s32[nt][2] + c23.x;
            s[nt][3] = s32[nt][3] + c23.y;
        }

        // ---- tail-tile masking (uniform branch; padded cols K=0 -> s=0)
        if (kt + 64 > nk) {
#pragma unroll
            for (int nt = 0; nt < 8; nt++) {
                int cb = kt + nt * 8 + 2 * gc;
                if (cb >= nk)     { s[nt][0] = -3.0e38f; s[nt][2] = -3.0e38f; }
                if (cb + 1 >= nk) { s[nt][1] = -3.0e38f; s[nt][3] = -3.0e38f; }
            }
        }

        // ---- row max (log2 domain)
        float mx0 = -3.0e38f, mx1 = -3.0e38f;
#pragma unroll
        for (int nt = 0; nt < 8; nt++) {
            mx0 = fmaxf(mx0, fmaxf(s[nt][0], s[nt][1]));
            mx1 = fmaxf(mx1, fmaxf(s[nt][2], s[nt][3]));
        }
        mx0 = fmaxf(mx0, __shfl_xor_sync(0xffffffffu, mx0, 1));
        mx0 = fmaxf(mx0, __shfl_xor_sync(0xffffffffu, mx0, 2));
        mx1 = fmaxf(mx1, __shfl_xor_sync(0xffffffffu, mx1, 1));
        mx1 = fmaxf(mx1, __shfl_xor_sync(0xffffffffu, mx1, 2));
        float mn0 = fmaxf(m0_, mx0), mn1 = fmaxf(m1_, mx1);
        float al0 = fexp2m(m0_ - mn0), al1 = fexp2m(m1_ - mn1);
        m0_ = mn0;
        m1_ = mn1;

        // ---- exp + sums + pack P into mma A-fragments (hi/lo)
        uint32_t pa_h[4][4], pa_l[4][4];
        float sm0 = 0.0f, sm1 = 0.0f;
#pragma unroll
        for (int nt = 0; nt < 8; nt++) {
            float p0 = fexp2m(s[nt][0] - mn0);
            float p1 = fexp2m(s[nt][1] - mn0);
            float p2 = fexp2m(s[nt][2] - mn1);
            float p3 = fexp2m(s[nt][3] - mn1);
            sm0 += p0 + p1;
            sm1 += p2 + p3;
            int kp = nt >> 1, q = nt & 1;
            __half2 hb01 = __floats2half2_rn(p0, p1);
            __half2 hb23 = __floats2half2_rn(p2, p3);
            pa_h[kp][q * 2 + 0] = *(uint32_t*)&hb01;
            pa_h[kp][q * 2 + 1] = *(uint32_t*)&hb23;
            float2 f01 = __half22float2(hb01);
            float2 f23 = __half22float2(hb23);
            __half2 lb01 = __floats2half2_rn(p0 - f01.x, p1 - f01.y);
            __half2 lb23 = __floats2half2_rn(p2 - f23.x, p3 - f23.y);
            pa_l[kp][q * 2 + 0] = *(uint32_t*)&lb01;
            pa_l[kp][q * 2 + 1] = *(uint32_t*)&lb23;
        }
        sm0 += __shfl_xor_sync(0xffffffffu, sm0, 1);
        sm0 += __shfl_xor_sync(0xffffffffu, sm0, 2);
        sm1 += __shfl_xor_sync(0xffffffffu, sm1, 1);
        sm1 += __shfl_xor_sync(0xffffffffu, sm1, 2);
        l0_ = l0_ * al0 + sm0;
        l1_ = l1_ * al1 + sm1;

#pragma unroll
        for (int j = 0; j < 8; j++) {
            o[j][0] *= al0;
            o[j][1] *= al0;
            o[j][2] *= al1;
            o[j][3] *= al1;
        }

        // ---- O += P @ V (f16x3: main f32-acc into o, corrections f16-acc)
        uint32_t oc[8][2];
#pragma unroll
        for (int j = 0; j < 8; j++) { oc[j][0] = 0u; oc[j][1] = 0u; }
        const uint32_t aVh = stg + 128 * ARB + bro, aVl = stg + 192 * ARB + bro;
#pragma unroll
        for (int kp = 0; kp < 4; kp++) {
            uint32_t vf[4][4];
#pragma unroll
            for (int nt2 = 0; nt2 < 4; nt2++)
                ldsm4(vf[nt2], aVh + nt2 * 16 * ARB + kp * 32);
#pragma unroll
            for (int nt2 = 0; nt2 < 4; nt2++)
#pragma unroll
                for (int q = 0; q < 2; q++)
                    mma_f32h(o[nt2 * 2 + q], pa_h[kp], &vf[nt2][q * 2]);
#pragma unroll
            for (int nt2 = 0; nt2 < 4; nt2++)
#pragma unroll
                for (int q = 0; q < 2; q++)
                    mma_f16a(oc[nt2 * 2 + q], pa_l[kp], &vf[nt2][q * 2]);
#pragma unroll
            for (int nt2 = 0; nt2 < 4; nt2++)
                ldsm4(vf[nt2], aVl + nt2 * 16 * ARB + kp * 32);
#pragma unroll
            for (int nt2 = 0; nt2 < 4; nt2++)
#pragma unroll
                for (int q = 0; q < 2; q++)
                    mma_f16a(oc[nt2 * 2 + q], pa_h[kp], &vf[nt2][q * 2]);
        }
        // merge PV corrections (this-iter terms, post-alpha scaling of o)
#pragma unroll
        for (int nt = 0; nt < 8; nt++) {
            float2 c01 = h2f2(oc[nt][0]);
            float2 c23 = h2f2(oc[nt][1]);
            o[nt][0] += c01.x;
            o[nt][1] += c01.y;
            o[nt][2] += c23.x;
            o[nt][3] += c23.y;
        }

        if (it + 1 < niter) {
            CP_WAIT0();
            __syncthreads();
        }
    }

    // ---- normalize + store half hi/lo split at (B, L, H*64) for out-proj
    float inv0 = (l0_ > 0.0f) ? 1.0f / l0_ : 0.0f;
    float inv1 = (l1_ > 0.0f) ? 1.0f / l1_ : 0.0f;
    int r0 = q0 + wid * 16 + gr, r1 = r0 + 8;
    size_t base0 = (size_t)(b * SEQ + r0) * D_MODEL + h * DK;
    size_t base1 = (size_t)(b * SEQ + r1) * D_MODEL + h * DK;
#pragma unroll
    for (int nt = 0; nt < 8; nt++) {
        int cl = nt * 8 + 2 * gc;
        float v0 = o[nt][0] * inv0, v1 = o[nt][1] * inv0;
        float v2 = o[nt][2] * inv1, v3 = o[nt][3] * inv1;
        __half2 h01 = __floats2half2_rn(v0, v1);
        __half2 h23 = __floats2half2_rn(v2, v3);
        float2 f01 = __half22float2(h01), f23 = __half22float2(h23);
        *(__half2*)(OutH + base0 + cl) = h01;
        *(__half2*)(OutL + base0 + cl) = __floats2half2_rn(v0 - f01.x, v1 - f01.y);
        *(__half2*)(OutH + base1 + cl) = h23;
        *(__half2*)(OutL + base1 + cl) = __floats2half2_rn(v2 - f23.x, v3 - f23.y);
    }
}

// ============================================================================
// Launch: 7 kernels total
// ============================================================================
extern "C" void kernel_launch(void* const* d_in, const int* in_sizes, int n_in,
                              void* d_out, int out_size) {
    const float* query = (const float*)d_in[0];
    const float* key   = (const float*)d_in[1];
    const float* value = (const float*)d_in[2];
    const int*   mask  = (const int*)d_in[3];
    const float* Wq = (const float*)d_in[4];
    const float* bq = (const float*)d_in[5];
    const float* Wk = (const float*)d_in[6];
    const float* bk = (const float*)d_in[7];
    const float* Wv = (const float*)d_in[8];
    const float* bv = (const float*)d_in[9];
    const float* Wo = (const float*)d_in[10];
    const float* bo = (const float*)d_in[11];

    __half *Ah, *Al, *Wth, *Wtl, *Qh, *Ql, *Kh, *Kl, *Khc, *Klc, *Vth, *Vtl;
    float *Vf;
    int *idx, *nk;
    cudaGetSymbolAddress((void**)&Ah, g_Ah);
    cudaGetSymbolAddress((void**)&Al, g_Al);
    cudaGetSymbolAddress((void**)&Wth, g_Wth);
    cudaGetSymbolAddress((void**)&Wtl, g_Wtl);
    cudaGetSymbolAddress((void**)&Qh, g_Qh);
    cudaGetSymbolAddress((void**)&Ql, g_Ql);
    cudaGetSymbolAddress((void**)&Kh, g_Kh);
    cudaGetSymbolAddress((void**)&Kl, g_Kl);
    cudaGetSymbolAddress((void**)&Khc, g_Khc);
    cudaGetSymbolAddress((void**)&Klc, g_Klc);
    cudaGetSymbolAddress((void**)&Vf, g_Vf);
    cudaGetSymbolAddress((void**)&Vth, g_Vth);
    cudaGetSymbolAddress((void**)&Vtl, g_Vtl);
    cudaGetSymbolAddress((void**)&idx, g_idx);
    cudaGetSymbolAddress((void**)&nk, g_nk);

    cudaFuncSetAttribute(mm_gemm, cudaFuncAttributeMaxDynamicSharedMemorySize,
                         G_SMEM);
    cudaFuncSetAttribute(mm_attn, cudaFuncAttributeMaxDynamicSharedMemorySize,
                         A_SMEM);

    const int N4 = MT * D_MODEL / 4;

    mask_scan_kernel<<<BATCH, 1024>>>(mask, idx, nk);
    wt_split_b_kernel<<<dim3(16, 16, 4), dim3(32, 32)>>>(Wq, Wk, Wv, Wo, Wth, Wtl);
    split_b_kernel<<<dim3(N4 / 256, 3), 256>>>((const float4*)query,
                                               (const float4*)key,
                                               (const float4*)value, Ah, Al, N4);
    mm_gemm<<<dim3(4, 64, 3), 256, G_SMEM>>>(Ah, Al, Wth, Wtl, bq, bk, bv, bo,
                                             Qh, Ql, Kh, Kl, Vf, nullptr, 0);
    kv_gather_kernel<<<dim3(SEQ / 64, BH), 256>>>(Kh, Kl, Vf, idx, nk,
                                                  Khc, Klc, Vth, Vtl);
    mm_attn<<<dim3(SEQ / 128, BH), 256, A_SMEM>>>(Qh, Ql, Khc, Klc, Vth, Vtl,
                                                  nk, Ah, Al);
    mm_gemm<<<dim3(4, 64, 1), 256, G_SMEM>>>(Ah, Al, Wth, Wtl, bq, bk, bv, bo,
                                             nullptr, nullptr, nullptr, nullptr,
                                             nullptr, (float*)d_out, 3);
}

// round 12
// speedup vs baseline: 1.4449x; 1.4449x over previous
#include <cuda_runtime.h>
#include <cuda_fp16.h>
#include <cstdint>

#define NUM_HEADS 8
#define D_MODEL   512
#define DK        64
#define SEQ       2048
#define BATCH     4
#define MT        (BATCH * SEQ)        // 8192
#define BH        (BATCH * NUM_HEADS)  // 32

// ============================================================================
// Scratch (device globals — no allocation allowed)
// ============================================================================
__device__ __align__(16) __half g_Ah[3 * MT * D_MODEL];
__device__ __align__(16) __half g_Al[3 * MT * D_MODEL];
__device__ __align__(16) __half g_Wth[4 * D_MODEL * D_MODEL];
__device__ __align__(16) __half g_Wtl[2 * D_MODEL * D_MODEL];  // lo only for Wq,Wk
__device__ __align__(16) __half g_Qh[BH * SEQ * DK];
__device__ __align__(16) __half g_Ql[BH * SEQ * DK];
__device__ __align__(16) __half g_Kh[BH * SEQ * DK];
__device__ __align__(16) __half g_Khc[BH * SEQ * DK];  // compacted K hi
__device__ __align__(16) float  g_Vf[BH * SEQ * DK];
__device__ __align__(16) __half g_Vth[BH * DK * SEQ];  // compacted V^T hi
__device__ int g_idx[BATCH * SEQ];
__device__ int g_nk[BATCH];

// 0.125 (1/sqrt(d_k)) * log2(e): folded into Q projection so S is in log2 units
#define QSCALE 0.18033688011117128f

// ============================================================================
// PTX primitives (all legal at compute_103 baseline)
// ============================================================================
__device__ __forceinline__ uint32_t smem_to_u32(const void* p) {
    uint32_t a;
    asm("{ .reg .u64 t; cvta.to.shared.u64 t, %1; cvt.u32.u64 %0, t; }"
        : "=r"(a) : "l"(p));
    return a;
}

__device__ __forceinline__ void ldsm4(uint32_t* r, uint32_t addr) {
    asm volatile("ldmatrix.sync.aligned.m8n8.x4.shared.b16 {%0,%1,%2,%3}, [%4];"
                 : "=r"(r[0]), "=r"(r[1]), "=r"(r[2]), "=r"(r[3]) : "r"(addr));
}

// f16 inputs, f32 accumulate
__device__ __forceinline__ void mma_f32h(float* c, const uint32_t* a,
                                         const uint32_t* b) {
    asm volatile(
        "mma.sync.aligned.m16n8k16.row.col.f32.f16.f16.f32 "
        "{%0,%1,%2,%3}, {%4,%5,%6,%7}, {%8,%9}, {%0,%1,%2,%3};"
        : "+f"(c[0]), "+f"(c[1]), "+f"(c[2]), "+f"(c[3])
        : "r"(a[0]), "r"(a[1]), "r"(a[2]), "r"(a[3]), "r"(b[0]), "r"(b[1]));
}

#define CP16(dst, src) \
    asm volatile("cp.async.cg.shared.global [%0], [%1], 16;" \
                 :: "r"(dst), "l"(src) : "memory")
#define CP_COMMIT() asm volatile("cp.async.commit_group;" ::: "memory")
#define CP_WAIT0()  asm volatile("cp.async.wait_group 0;" ::: "memory")

// exp2 via magic-constant round + degree-4 poly on [-0.5, 0.5]; t <= 0.
__device__ __forceinline__ float fexp2m(float t) {
    t = fmaxf(t, -126.0f);
    float z = t + 12582912.0f;
    float f = t - (z - 12582912.0f);
    float p = fmaf(f, 0.0096181291f, 0.0555041087f);
    p = fmaf(p, f, 0.2402265069f);
    p = fmaf(p, f, 0.6931471806f);
    p = fmaf(p, f, 1.0f);
    uint32_t sb = (uint32_t)((__float_as_int(z) + 127) << 23);
    return __int_as_float(sb) * p;
}

// ============================================================================
// Mask prefix scan
// ============================================================================
__global__ __launch_bounds__(1024) void mask_scan_kernel(
    const int* __restrict__ mask, int* __restrict__ idx, int* __restrict__ nk) {
    const int b = blockIdx.x, tid = threadIdx.x;
    const int lane = tid & 31, w = tid >> 5;
    const int* mp = mask + b * SEQ;
    int e0 = (mp[2 * tid] != 0), e1 = (mp[2 * tid + 1] != 0);
    int tsum = e0 + e1;
    int v = tsum;
#pragma unroll
    for (int o = 1; o < 32; o <<= 1) {
        int u = __shfl_up_sync(0xffffffffu, v, o);
        if (lane >= o) v += u;
    }
    __shared__ int ws[32];
    if (lane == 31) ws[w] = v;
    __syncthreads();
    if (w == 0) {
        int x = ws[lane];
#pragma unroll
        for (int o = 1; o < 32; o <<= 1) {
            int u = __shfl_up_sync(0xffffffffu, x, o);
            if (lane >= o) x += u;
        }
        ws[lane] = x;
    }
    __syncthreads();
    int base = ((w > 0) ? ws[w - 1] : 0) + (v - tsum);
    if (e0) idx[b * SEQ + base] = 2 * tid;
    if (e1) idx[b * SEQ + base + e0] = 2 * tid + 1;
    if (tid == 0) nk[b] = ws[31];
}

// ============================================================================
// KV gather: pack unmasked K rows (hi) densely; gather+transpose V (hi).
// ============================================================================
__global__ __launch_bounds__(256) void kv_gather_kernel(
    const __half* __restrict__ Kh, const float* __restrict__ Vf,
    const int* __restrict__ idx, const int* __restrict__ nk,
    __half* __restrict__ Khc, __half* __restrict__ Vth) {
    const int t = blockIdx.x, bh = blockIdx.y, b = bh >> 3;
    const int tid = threadIdx.x;
    const int n = nk[b];
    const int j0 = t * 64;
    if (j0 >= ((n + 63) & ~63)) return;
    const int* idxb = idx + b * SEQ;

    const uint4 z4 = make_uint4(0, 0, 0, 0);
#pragma unroll
    for (int t2 = 0; t2 < 2; t2++) {
        int i = tid + t2 * 256;
        int r = i >> 3, j = i & 7;
        int jj = j0 + r;
        int row = (jj < n) ? idxb[jj] : -1;
        size_t src = ((size_t)bh * SEQ + row) * DK + j * 8;
        size_t dst = ((size_t)bh * SEQ + jj) * DK + j * 8;
        *(uint4*)(Khc + dst) = (row >= 0) ? *(const uint4*)(Kh + src) : z4;
    }

    __shared__ float ts[64][65];
    for (int i = tid; i < 4096; i += 256) {
        int r = i >> 6, c = i & 63;
        int jj = j0 + r;
        int row = (jj < n) ? idxb[jj] : -1;
        ts[r][c] = (row >= 0) ? Vf[((size_t)bh * SEQ + row) * DK + c] : 0.0f;
    }
    __syncthreads();
    for (int i = tid; i < 4096; i += 256) {
        int d = i >> 6, c = i & 63;
        Vth[((size_t)bh * DK + d) * SEQ + j0 + c] = __float2half_rn(ts[c][d]);
    }
}

// ============================================================================
// Prep kernels
// ============================================================================
__global__ void split_b_kernel(const float4* __restrict__ q,
                               const float4* __restrict__ k,
                               const float4* __restrict__ v,
                               __half* __restrict__ Ah,
                               __half* __restrict__ Al, int n4) {
    int i = blockIdx.x * blockDim.x + threadIdx.x;
    if (i >= n4) return;
    int z = blockIdx.y;
    const float4* in = (z == 0) ? q : (z == 1) ? k : v;
    __half2* hi = (__half2*)(Ah + (size_t)z * MT * D_MODEL);
    __half2* lo = (__half2*)(Al + (size_t)z * MT * D_MODEL);
    float4 vv = in[i];
    __half2 h01 = __floats2half2_rn(vv.x, vv.y);
    __half2 h23 = __floats2half2_rn(vv.z, vv.w);
    hi[2 * i]     = h01;
    hi[2 * i + 1] = h23;
    float2 f01 = __half22float2(h01), f23 = __half22float2(h23);
    lo[2 * i]     = __floats2half2_rn(vv.x - f01.x, vv.y - f01.y);
    lo[2 * i + 1] = __floats2half2_rn(vv.z - f23.x, vv.w - f23.y);
}

// W lo stored only for z<2 (Wq, Wk) — value chain uses hi-only weights.
__global__ void wt_split_b_kernel(const float* __restrict__ W0,
                                  const float* __restrict__ W1,
                                  const float* __restrict__ W2,
                                  const float* __restrict__ W3,
                                  __half* __restrict__ Wth,
                                  __half* __restrict__ Wtl) {
    __shared__ float ts[32][33];
    int z = blockIdx.z;
    const float* W = (z == 0) ? W0 : (z == 1) ? W1 : (z == 2) ? W2 : W3;
    __half* oh = Wth + (size_t)z * D_MODEL * D_MODEL;
    int n0 = blockIdx.x * 32, k0 = blockIdx.y * 32;
    ts[threadIdx.y][threadIdx.x] = W[(size_t)(k0 + threadIdx.y) * 512 + n0 + threadIdx.x];
    __syncthreads();
    int n = n0 + threadIdx.y, k = k0 + threadIdx.x;
    float v = ts[threadIdx.x][threadIdx.y];
    __half hv = __float2half_rn(v);
    oh[(size_t)n * 512 + k] = hv;
    if (z < 2) {
        __half* ol = Wtl + (size_t)z * D_MODEL * D_MODEL;
        ol[(size_t)n * 512 + k] = __float2half_rn(v - __half2float(hv));
    }
}

// ============================================================================
// HMMA GEMM (cp.async double-buffered), f16, all f32-acc.
// z=0 (Q), z=1 (K): 3 passes (Ah·Bh + Al·Bh + Ah·Bl).
// z=2 (V), z=3 (out proj): 2 passes (Ah·Bh + Al·Bh), Bl never loaded.
// ============================================================================
#define GRB    80      // smem row bytes (40 halves)
#define GTILE  10240   // 128 rows
#define GSTAGE 40960   // 4 tiles
#define G_SMEM (2 * GSTAGE)

__global__ __launch_bounds__(256, 2) void mm_gemm(
    const __half* __restrict__ Ahb, const __half* __restrict__ Alb,
    const __half* __restrict__ Wthb, const __half* __restrict__ Wtlb,
    const float* __restrict__ bq, const float* __restrict__ bk,
    const float* __restrict__ bv, const float* __restrict__ bo,
    __half* __restrict__ Qh, __half* __restrict__ Ql,
    __half* __restrict__ Kh,
    float* __restrict__ Vf, float* __restrict__ dout, int zofs) {
    extern __shared__ __align__(16) char smg[];
    const int tid = threadIdx.x, wid = tid >> 5, lane = tid & 31;
    const int wm = wid >> 1, wn = wid & 1;
    const int gr = lane >> 2, gc = lane & 3;
    const int m0 = blockIdx.y * 128, n0 = blockIdx.x * 128;
    const int z = blockIdx.z + zofs;
    const bool need_bl = (z <= 1);

    const __half* Ah = Ahb + (size_t)((z == 3) ? 0 : z) * MT * D_MODEL;
    const __half* Al = Alb + (size_t)((z == 3) ? 0 : z) * MT * D_MODEL;
    const __half* Bh = Wthb + (size_t)z * D_MODEL * D_MODEL;
    const __half* Bl = Wtlb + (size_t)((z <= 1) ? z : 0) * D_MODEL * D_MODEL;
    const float* bias = (z == 0) ? bq : (z == 1) ? bk : (z == 2) ? bv : bo;

    const uint32_t sb = smem_to_u32(smg);
    const uint32_t rAh = (uint32_t)(wm * 32 + (lane & 15)) * GRB + (((lane >> 4) & 1) << 4);
    const uint32_t rBh = 2u * GTILE +
        (uint32_t)(wn * 64 + (lane & 7) + (((lane >> 4) & 1) << 3)) * GRB +
        (((lane >> 3) & 1) << 4);

    const int pr = tid >> 2, pj = tid & 3;
    const uint32_t poff = (uint32_t)pr * GRB + pj * 16;

    float c[2][8][4];
#pragma unroll
    for (int i = 0; i < 2; i++)
#pragma unroll
        for (int j = 0; j < 8; j++)
#pragma unroll
            for (int e = 0; e < 4; e++) c[i][j][e] = 0.0f;

    {
#pragma unroll
        for (int t = 0; t < 2; t++) {
            int r = pr + t * 64;
            uint32_t d = sb + poff + (uint32_t)t * 64 * GRB;
            size_t ga = (size_t)(m0 + r) * 512 + pj * 8;
            size_t gb = (size_t)(n0 + r) * 512 + pj * 8;
            CP16(d, Ah + ga);
            CP16(d + GTILE, Al + ga);
            CP16(d + 2 * GTILE, Bh + gb);
            if (need_bl) CP16(d + 3 * GTILE, Bl + gb);
        }
        CP_COMMIT();
    }

    for (int kc = 0; kc < 16; kc++) {
        const uint32_t stg = sb + (uint32_t)(kc & 1) * GSTAGE;
        CP_WAIT0();
        __syncthreads();
        if (kc < 15) {
            const int k0 = (kc + 1) * 32;
            const uint32_t nstg = sb + (uint32_t)((kc + 1) & 1) * GSTAGE;
#pragma unroll
            for (int t = 0; t < 2; t++) {
                int r = pr + t * 64;
                uint32_t d = nstg + poff + (uint32_t)t * 64 * GRB;
                size_t ga = (size_t)(m0 + r) * 512 + k0 + pj * 8;
                size_t gb = (size_t)(n0 + r) * 512 + k0 + pj * 8;
                CP16(d, Ah + ga);
                CP16(d + GTILE, Al + ga);
                CP16(d + 2 * GTILE, Bh + gb);
                if (need_bl) CP16(d + 3 * GTILE, Bl + gb);
            }
            CP_COMMIT();
        }

        const uint32_t aAh = stg + rAh, aBh = stg + rBh;
#pragma unroll
        for (int ks = 0; ks < 2; ks++) {
            uint32_t ah[2][4], al[2][4], bfr[4][4];
            ldsm4(ah[0], aAh + ks * 32);
            ldsm4(ah[1], aAh + 16 * GRB + ks * 32);
            ldsm4(al[0], aAh + GTILE + ks * 32);
            ldsm4(al[1], aAh + GTILE + 16 * GRB + ks * 32);
#pragma unroll
            for (int nt2 = 0; nt2 < 4; nt2++)
                ldsm4(bfr[nt2], aBh + nt2 * 16 * GRB + ks * 32);
            // pass 1: Ah*Bh
#pragma unroll
            for (int nt2 = 0; nt2 < 4; nt2++)
#pragma unroll
                for (int q = 0; q < 2; q++)
#pragma unroll
                    for (int mt = 0; mt < 2; mt++)
                        mma_f32h(c[mt][nt2 * 2 + q], ah[mt], &bfr[nt2][q * 2]);
            // pass 2: Al*Bh
#pragma unroll
            for (int nt2 = 0; nt2 < 4; nt2++)
#pragma unroll
                for (int q = 0; q < 2; q++)
#pragma unroll
                    for (int mt = 0; mt < 2; mt++)
                        mma_f32h(c[mt][nt2 * 2 + q], al[mt], &bfr[nt2][q * 2]);
            // pass 3 (Q/K projections only): Ah*Bl
            if (need_bl) {
#pragma unroll
                for (int nt2 = 0; nt2 < 4; nt2++)
                    ldsm4(bfr[nt2], aBh + GTILE + nt2 * 16 * GRB + ks * 32);
#pragma unroll
                for (int nt2 = 0; nt2 < 4; nt2++)
#pragma unroll
                    for (int q = 0; q < 2; q++)
#pragma unroll
                        for (int mt = 0; mt < 2; mt++)
                            mma_f32h(c[mt][nt2 * 2 + q], ah[mt], &bfr[nt2][q * 2]);
            }
        }
    }

    // Epilogue
#pragma unroll
    for (int mt = 0; mt < 2; mt++) {
#pragma unroll
        for (int half_ = 0; half_ < 2; half_++) {
            int m = m0 + wm * 32 + mt * 16 + gr + half_ * 8;
            int bb = m >> 11, l = m & 2047;
#pragma unroll
            for (int nt = 0; nt < 8; nt++) {
                int n = n0 + wn * 64 + nt * 8 + 2 * gc;
                float v0 = c[mt][nt][half_ * 2 + 0] + bias[n];
                float v1 = c[mt][nt][half_ * 2 + 1] + bias[n + 1];
                if (z == 3) {
                    *(float2*)(dout + (size_t)m * 512 + n) = make_float2(v0, v1);
                } else if (z == 2) {
                    int h = n >> 6, d = n & 63;
                    *(float2*)(Vf + ((size_t)(bb * 8 + h) * SEQ + l) * DK + d) =
                        make_float2(v0, v1);
                } else if (z == 1) {
                    int h = n >> 6, d = n & 63;
                    size_t o = ((size_t)(bb * 8 + h) * SEQ + l) * DK + d;
                    *(__half2*)(Kh + o) = __floats2half2_rn(v0, v1);
                } else {
                    v0 *= QSCALE; v1 *= QSCALE;
                    int h = n >> 6, d = n & 63;
                    size_t o = ((size_t)(bb * 8 + h) * SEQ + l) * DK + d;
                    __half2 hh = __floats2half2_rn(v0, v1);
                    float2 hf = __half22float2(hh);
                    *(__half2*)(Qh + o) = hh;
                    *(__half2*)(Ql + o) = __floats2half2_rn(v0 - hf.x, v1 - hf.y);
                }
            }
        }
    }
}

// ============================================================================
// HMMA flash attention over compacted KV.
// QK = Qh·Kh + Ql·Kh (2-pass, K hi only); PV = Ph·Vh + Pl·Vh (2-pass, V hi).
// All f32-acc. 2 CTAs/SM; Q in smem; log2-domain scores; magic exp2.
// ============================================================================
#define ARB   144                 // smem row bytes (72 halves)
#define ATILE (128 * ARB)         // one stage: KH(64 rows) + VH(64 rows)
#define QOFF  (2 * ATILE)         // Q region: QH(128) QL(128)
#define A_SMEM (2 * ATILE + 256 * ARB)   // 73728 bytes

__global__ __launch_bounds__(256, 2) void mm_attn(
    const __half* __restrict__ Qh, const __half* __restrict__ Ql,
    const __half* __restrict__ Kh, const __half* __restrict__ Vh,
    const int* __restrict__ nkp,
    __half* __restrict__ OutH, __half* __restrict__ OutL) {
    extern __shared__ __align__(16) char smA[];

    const int tid = threadIdx.x, wid = tid >> 5, lane = tid & 31;
    const int gr = lane >> 2, gc = lane & 3;
    const int q0 = blockIdx.x * 128;
    const int bh = blockIdx.y, b = bh >> 3, h = bh & 7;
    const int nk = nkp[b];
    const int niter = (nk + 63) >> 6;

    const __half* Qhp = Qh + (size_t)bh * SEQ * DK;
    const __half* Qlp = Ql + (size_t)bh * SEQ * DK;
    const __half* Khp = Kh + (size_t)bh * SEQ * DK;
    const __half* Vhp = Vh + (size_t)bh * DK * SEQ;

    const uint32_t sb = smem_to_u32(smA);
    const int pr = tid >> 3, pj = tid & 7;   // 32 rows x 8 chunks per pass

    // ---- prefetch KV tile 0 into stage 0 (K rows 0-63, V rows 64-127)
    if (niter > 0) {
#pragma unroll
        for (int t = 0; t < 4; t++) {
            int r = pr + t * 32;
            uint32_t d = sb + (uint32_t)r * ARB + pj * 16;
            if (r < 64)
                CP16(d, Khp + (size_t)r * DK + pj * 8);
            else
                CP16(d, Vhp + (size_t)(r - 64) * SEQ + pj * 8);
        }
        CP_COMMIT();
    }

    // ---- stage Q (persistent region)
#pragma unroll
    for (int t = 0; t < 4; t++) {
        int i = tid + t * 256;
        int r = i >> 3, j = i & 7;
        char* dsth = smA + QOFF + (size_t)r * ARB + j * 16;
        char* dstl = smA + QOFF + (size_t)(128 + r) * ARB + j * 16;
        *(uint4*)dsth = *(const uint4*)(Qhp + (size_t)(q0 + r) * DK + j * 8);
        *(uint4*)dstl = *(const uint4*)(Qlp + (size_t)(q0 + r) * DK + j * 8);
    }
    CP_WAIT0();
    __syncthreads();

    const uint32_t aQb = sb + QOFF +
        (uint32_t)(wid * 16 + (lane & 15)) * ARB + (((lane >> 4) & 1) << 4);
    const uint32_t bro = (uint32_t)((lane & 7) + (((lane >> 4) & 1) << 3)) * ARB +
                         (((lane >> 3) & 1) << 4);

    float m0_ = -1e30f, m1_ = -1e30f, l0_ = 0.0f, l1_ = 0.0f;
    float o[8][4];
#pragma unroll
    for (int j = 0; j < 8; j++)
#pragma unroll
        for (int e = 0; e < 4; e++) o[j][e] = 0.0f;

    for (int it = 0; it < niter; it++) {
        const int cur = it & 1;
        const uint32_t stg = sb + (uint32_t)cur * ATILE;
        const int kt = it * 64;

        if (it + 1 < niter) {
            const int ktn = kt + 64;
            const uint32_t nstg = sb + (uint32_t)(1 - cur) * ATILE;
#pragma unroll
            for (int t = 0; t < 4; t++) {
                int r = pr + t * 32;
                uint32_t d = nstg + (uint32_t)r * ARB + pj * 16;
                if (r < 64)
                    CP16(d, Khp + (size_t)(ktn + r) * DK + pj * 8);
                else
                    CP16(d, Vhp + (size_t)(r - 64) * SEQ + ktn + pj * 8);
            }
            CP_COMMIT();
        }

        // ---- S = Qh·Kh + Ql·Kh (f32 acc; log2 units)
        float s[8][4];
#pragma unroll
        for (int j = 0; j < 8; j++)
#pragma unroll
            for (int e = 0; e < 4; e++) s[j][e] = 0.0f;
        const uint32_t aKh = stg + bro;
#pragma unroll
        for (int ks = 0; ks < 4; ks++) {
            uint32_t qhf[4], qlf[4], kf[4][4];
            ldsm4(qhf, aQb + ks * 32);
            ldsm4(qlf, aQb + 128 * ARB + ks * 32);
#pragma unroll
            for (int nt2 = 0; nt2 < 4; nt2++)
                ldsm4(kf[nt2], aKh + nt2 * 16 * ARB + ks * 32);
#pragma unroll
            for (int nt2 = 0; nt2 < 4; nt2++)
#pragma unroll
                for (int q = 0; q < 2; q++)
                    mma_f32h(s[nt2 * 2 + q], qhf, &kf[nt2][q * 2]);
#pragma unroll
            for (int nt2 = 0; nt2 < 4; nt2++)
#pragma unroll
                for (int q = 0; q < 2; q++)
                    mma_f32h(s[nt2 * 2 + q], qlf, &kf[nt2][q * 2]);
        }

        // ---- tail-tile masking (uniform branch; padded cols K=0 -> s=0)
        if (kt + 64 > nk) {
#pragma unroll
            for (int nt = 0; nt < 8; nt++) {
                int cb = kt + nt * 8 + 2 * gc;
                if (cb >= nk)     { s[nt][0] = -3.0e38f; s[nt][2] = -3.0e38f; }
                if (cb + 1 >= nk) { s[nt][1] = -3.0e38f; s[nt][3] = -3.0e38f; }
            }
        }

        // ---- row max (log2 domain)
        float mx0 = -3.0e38f, mx1 = -3.0e38f;
#pragma unroll
        for (int nt = 0; nt < 8; nt++) {
            mx0 = fmaxf(mx0, fmaxf(s[nt][0], s[nt][1]));
            mx1 = fmaxf(mx1, fmaxf(s[nt][2], s[nt][3]));
        }
        mx0 = fmaxf(mx0, __shfl_xor_sync(0xffffffffu, mx0, 1));
        mx0 = fmaxf(mx0, __shfl_xor_sync(0xffffffffu, mx0, 2));
        mx1 = fmaxf(mx1, __shfl_xor_sync(0xffffffffu, mx1, 1));
        mx1 = fmaxf(mx1, __shfl_xor_sync(0xffffffffu, mx1, 2));
        float mn0 = fmaxf(m0_, mx0), mn1 = fmaxf(m1_, mx1);
        float al0 = fexp2m(m0_ - mn0), al1 = fexp2m(m1_ - mn1);
        m0_ = mn0;
        m1_ = mn1;

        // ---- exp + sums + pack P into mma A-fragments (hi/lo)
        uint32_t pa_h[4][4], pa_l[4][4];
        float sm0 = 0.0f, sm1 = 0.0f;
#pragma unroll
        for (int nt = 0; nt < 8; nt++) {
            float p0 = fexp2m(s[nt][0] - mn0);
            float p1 = fexp2m(s[nt][1] - mn0);
            float p2 = fexp2m(s[nt][2] - mn1);
            float p3 = fexp2m(s[nt][3] - mn1);
            sm0 += p0 + p1;
            sm1 += p2 + p3;
            int kp = nt >> 1, q = nt & 1;
            __half2 hb01 = __floats2half2_rn(p0, p1);
            __half2 hb23 = __floats2half2_rn(p2, p3);
            pa_h[kp][q * 2 + 0] = *(uint32_t*)&hb01;
            pa_h[kp][q * 2 + 1] = *(uint32_t*)&hb23;
            float2 f01 = __half22float2(hb01);
            float2 f23 = __half22float2(hb23);
            __half2 lb01 = __floats2half2_rn(p0 - f01.x, p1 - f01.y);
            __half2 lb23 = __floats2half2_rn(p2 - f23.x, p3 - f23.y);
            pa_l[kp][q * 2 + 0] = *(uint32_t*)&lb01;
            pa_l[kp][q * 2 + 1] = *(uint32_t*)&lb23;
        }
        sm0 += __shfl_xor_sync(0xffffffffu, sm0, 1);
        sm0 += __shfl_xor_sync(0xffffffffu, sm0, 2);
        sm1 += __shfl_xor_sync(0xffffffffu, sm1, 1);
        sm1 += __shfl_xor_sync(0xffffffffu, sm1, 2);
        l0_ = l0_ * al0 + sm0;
        l1_ = l1_ * al1 + sm1;

#pragma unroll
        for (int j = 0; j < 8; j++) {
            o[j][0] *= al0;
            o[j][1] *= al0;
            o[j][2] *= al1;
            o[j][3] *= al1;
        }

        // ---- O += Ph·Vh + Pl·Vh (f32 acc)
        const uint32_t aVh = stg + 64 * ARB + bro;
#pragma unroll
        for (int kp = 0; kp < 4; kp++) {
            uint32_t vf[4][4];
#pragma unroll
            for (int nt2 = 0; nt2 < 4; nt2++)
                ldsm4(vf[nt2], aVh + nt2 * 16 * ARB + kp * 32);
#pragma unroll
            for (int nt2 = 0; nt2 < 4; nt2++)
#pragma unroll
                for (int q = 0; q < 2; q++)
                    mma_f32h(o[nt2 * 2 + q], pa_h[kp], &vf[nt2][q * 2]);
#pragma unroll
            for (int nt2 = 0; nt2 < 4; nt2++)
#pragma unroll
                for (int q = 0; q < 2; q++)
                    mma_f32h(o[nt2 * 2 + q], pa_l[kp], &vf[nt2][q * 2]);
        }

        if (it + 1 < niter) {
            CP_WAIT0();
            __syncthreads();
        }
    }

    // ---- normalize + store half hi/lo split at (B, L, H*64) for out-proj
    float inv0 = (l0_ > 0.0f) ? 1.0f / l0_ : 0.0f;
    float inv1 = (l1_ > 0.0f) ? 1.0f / l1_ : 0.0f;
    int r0 = q0 + wid * 16 + gr, r1 = r0 + 8;
    size_t base0 = (size_t)(b * SEQ + r0) * D_MODEL + h * DK;
    size_t base1 = (size_t)(b * SEQ + r1) * D_MODEL + h * DK;
#pragma unroll
    for (int nt = 0; nt < 8; nt++) {
        int cl = nt * 8 + 2 * gc;
        float v0 = o[nt][0] * inv0, v1 = o[nt][1] * inv0;
        float v2 = o[nt][2] * inv1, v3 = o[nt][3] * inv1;
        __half2 h01 = __floats2half2_rn(v0, v1);
        __half2 h23 = __floats2half2_rn(v2, v3);
        float2 f01 = __half22float2(h01), f23 = __half22float2(h23);
        *(__half2*)(OutH + base0 + cl) = h01;
        *(__half2*)(OutL + base0 + cl) = __floats2half2_rn(v0 - f01.x, v1 - f01.y);
        *(__half2*)(OutH + base1 + cl) = h23;
        *(__half2*)(OutL + base1 + cl) = __floats2half2_rn(v2 - f23.x, v3 - f23.y);
    }
}

// ============================================================================
// Launch: 7 kernels total
// ============================================================================
extern "C" void kernel_launch(void* const* d_in, const int* in_sizes, int n_in,
                              void* d_out, int out_size) {
    const float* query = (const float*)d_in[0];
    const float* key   = (const float*)d_in[1];
    const float* value = (const float*)d_in[2];
    const int*   mask  = (const int*)d_in[3];
    const float* Wq = (const float*)d_in[4];
    const float* bq = (const float*)d_in[5];
    const float* Wk = (const float*)d_in[6];
    const float* bk = (const float*)d_in[7];
    const float* Wv = (const float*)d_in[8];
    const float* bv = (const float*)d_in[9];
    const float* Wo = (const float*)d_in[10];
    const float* bo = (const float*)d_in[11];

    __half *Ah, *Al, *Wth, *Wtl, *Qh, *Ql, *Kh, *Khc, *Vth;
    float *Vf;
    int *idx, *nk;
    cudaGetSymbolAddress((void**)&Ah, g_Ah);
    cudaGetSymbolAddress((void**)&Al, g_Al);
    cudaGetSymbolAddress((void**)&Wth, g_Wth);
    cudaGetSymbolAddress((void**)&Wtl, g_Wtl);
    cudaGetSymbolAddress((void**)&Qh, g_Qh);
    cudaGetSymbolAddress((void**)&Ql, g_Ql);
    cudaGetSymbolAddress((void**)&Kh, g_Kh);
    cudaGetSymbolAddress((void**)&Khc, g_Khc);
    cudaGetSymbolAddress((void**)&Vf, g_Vf);
    cudaGetSymbolAddress((void**)&Vth, g_Vth);
    cudaGetSymbolAddress((void**)&idx, g_idx);
    cudaGetSymbolAddress((void**)&nk, g_nk);

    cudaFuncSetAttribute(mm_gemm, cudaFuncAttributeMaxDynamicSharedMemorySize,
                         G_SMEM);
    cudaFuncSetAttribute(mm_attn, cudaFuncAttributeMaxDynamicSharedMemorySize,
                         A_SMEM);

    const int N4 = MT * D_MODEL / 4;

    mask_scan_kernel<<<BATCH, 1024>>>(mask, idx, nk);
    wt_split_b_kernel<<<dim3(16, 16, 4), dim3(32, 32)>>>(Wq, Wk, Wv, Wo, Wth, Wtl);
    split_b_kernel<<<dim3(N4 / 256, 3), 256>>>((const float4*)query,
                                               (const float4*)key,
                                               (const float4*)value, Ah, Al, N4);
    mm_gemm<<<dim3(4, 64, 3), 256, G_SMEM>>>(Ah, Al, Wth, Wtl, bq, bk, bv, bo,
                                             Qh, Ql, Kh, Vf, nullptr, 0);
    kv_gather_kernel<<<dim3(SEQ / 64, BH), 256>>>(Kh, Vf, idx, nk, Khc, Vth);
    mm_attn<<<dim3(SEQ / 128, BH), 256, A_SMEM>>>(Qh, Ql, Khc, Vth, nk, Ah, Al);
    mm_gemm<<<dim3(4, 64, 1), 256, G_SMEM>>>(Ah, Al, Wth, Wtl, bq, bk, bv, bo,
                                             nullptr, nullptr, nullptr, nullptr,
                                             (float*)d_out, 3);
}

// round 13
// speedup vs baseline: 1.6667x; 1.1535x over previous
#include <cuda_runtime.h>
#include <cuda_fp16.h>
#include <cstdint>

#define NUM_HEADS 8
#define D_MODEL   512
#define DK        64
#define SEQ       2048
#define BATCH     4
#define MT        (BATCH * SEQ)        // 8192
#define BH        (BATCH * NUM_HEADS)  // 32

// ============================================================================
// Scratch (device globals — no allocation allowed)
// ============================================================================
__device__ __align__(16) __half g_Ah[3 * MT * D_MODEL];
__device__ __align__(16) __half g_Al[3 * MT * D_MODEL];
__device__ __align__(16) __half g_Wth[4 * D_MODEL * D_MODEL];
__device__ __align__(16) __half g_Qh[BH * SEQ * DK];
__device__ __align__(16) __half g_Ql[BH * SEQ * DK];
__device__ __align__(16) __half g_Kh[BH * SEQ * DK];
__device__ __align__(16) __half g_Khc[BH * SEQ * DK];  // compacted K hi
__device__ __align__(16) float  g_Vf[BH * SEQ * DK];
__device__ __align__(16) __half g_Vth[BH * DK * SEQ];  // compacted V^T hi
__device__ int g_idx[BATCH * SEQ];
__device__ int g_nk[BATCH];

// 0.125 (1/sqrt(d_k)) * log2(e): folded into Q projection so S is in log2 units
#define QSCALE 0.18033688011117128f

// ============================================================================
// PTX primitives (all legal at compute_103 baseline)
// ============================================================================
__device__ __forceinline__ uint32_t smem_to_u32(const void* p) {
    uint32_t a;
    asm("{ .reg .u64 t; cvta.to.shared.u64 t, %1; cvt.u32.u64 %0, t; }"
        : "=r"(a) : "l"(p));
    return a;
}

__device__ __forceinline__ void ldsm4(uint32_t* r, uint32_t addr) {
    asm volatile("ldmatrix.sync.aligned.m8n8.x4.shared.b16 {%0,%1,%2,%3}, [%4];"
                 : "=r"(r[0]), "=r"(r[1]), "=r"(r[2]), "=r"(r[3]) : "r"(addr));
}

// f16 inputs, f32 accumulate
__device__ __forceinline__ void mma_f32h(float* c, const uint32_t* a,
                                         const uint32_t* b) {
    asm volatile(
        "mma.sync.aligned.m16n8k16.row.col.f32.f16.f16.f32 "
        "{%0,%1,%2,%3}, {%4,%5,%6,%7}, {%8,%9}, {%0,%1,%2,%3};"
        : "+f"(c[0]), "+f"(c[1]), "+f"(c[2]), "+f"(c[3])
        : "r"(a[0]), "r"(a[1]), "r"(a[2]), "r"(a[3]), "r"(b[0]), "r"(b[1]));
}

#define CP16(dst, src) \
    asm volatile("cp.async.cg.shared.global [%0], [%1], 16;" \
                 :: "r"(dst), "l"(src) : "memory")
#define CP_COMMIT() asm volatile("cp.async.commit_group;" ::: "memory")
#define CP_WAIT0()  asm volatile("cp.async.wait_group 0;" ::: "memory")

// exp2 via magic-constant round + degree-4 poly on [-0.5, 0.5]; t <= 0.
__device__ __forceinline__ float fexp2m(float t) {
    t = fmaxf(t, -126.0f);
    float z = t + 12582912.0f;
    float f = t - (z - 12582912.0f);
    float p = fmaf(f, 0.0096181291f, 0.0555041087f);
    p = fmaf(p, f, 0.2402265069f);
    p = fmaf(p, f, 0.6931471806f);
    p = fmaf(p, f, 1.0f);
    uint32_t sb = (uint32_t)((__float_as_int(z) + 127) << 23);
    return __int_as_float(sb) * p;
}

// ============================================================================
// Mask prefix scan
// ============================================================================
__global__ __launch_bounds__(1024) void mask_scan_kernel(
    const int* __restrict__ mask, int* __restrict__ idx, int* __restrict__ nk) {
    const int b = blockIdx.x, tid = threadIdx.x;
    const int lane = tid & 31, w = tid >> 5;
    const int* mp = mask + b * SEQ;
    int e0 = (mp[2 * tid] != 0), e1 = (mp[2 * tid + 1] != 0);
    int tsum = e0 + e1;
    int v = tsum;
#pragma unroll
    for (int o = 1; o < 32; o <<= 1) {
        int u = __shfl_up_sync(0xffffffffu, v, o);
        if (lane >= o) v += u;
    }
    __shared__ int ws[32];
    if (lane == 31) ws[w] = v;
    __syncthreads();
    if (w == 0) {
        int x = ws[lane];
#pragma unroll
        for (int o = 1; o < 32; o <<= 1) {
            int u = __shfl_up_sync(0xffffffffu, x, o);
            if (lane >= o) x += u;
        }
        ws[lane] = x;
    }
    __syncthreads();
    int base = ((w > 0) ? ws[w - 1] : 0) + (v - tsum);
    if (e0) idx[b * SEQ + base] = 2 * tid;
    if (e1) idx[b * SEQ + base + e0] = 2 * tid + 1;
    if (tid == 0) nk[b] = ws[31];
}

// ============================================================================
// KV gather: pack unmasked K rows (hi) densely; gather+transpose V (hi).
// ============================================================================
__global__ __launch_bounds__(256) void kv_gather_kernel(
    const __half* __restrict__ Kh, const float* __restrict__ Vf,
    const int* __restrict__ idx, const int* __restrict__ nk,
    __half* __restrict__ Khc, __half* __restrict__ Vth) {
    const int t = blockIdx.x, bh = blockIdx.y, b = bh >> 3;
    const int tid = threadIdx.x;
    const int n = nk[b];
    const int j0 = t * 64;
    if (j0 >= ((n + 63) & ~63)) return;
    const int* idxb = idx + b * SEQ;

    const uint4 z4 = make_uint4(0, 0, 0, 0);
#pragma unroll
    for (int t2 = 0; t2 < 2; t2++) {
        int i = tid + t2 * 256;
        int r = i >> 3, j = i & 7;
        int jj = j0 + r;
        int row = (jj < n) ? idxb[jj] : -1;
        size_t src = ((size_t)bh * SEQ + row) * DK + j * 8;
        size_t dst = ((size_t)bh * SEQ + jj) * DK + j * 8;
        *(uint4*)(Khc + dst) = (row >= 0) ? *(const uint4*)(Kh + src) : z4;
    }

    __shared__ float ts[64][65];
    for (int i = tid; i < 4096; i += 256) {
        int r = i >> 6, c = i & 63;
        int jj = j0 + r;
        int row = (jj < n) ? idxb[jj] : -1;
        ts[r][c] = (row >= 0) ? Vf[((size_t)bh * SEQ + row) * DK + c] : 0.0f;
    }
    __syncthreads();
    for (int i = tid; i < 4096; i += 256) {
        int d = i >> 6, c = i & 63;
        Vth[((size_t)bh * DK + d) * SEQ + j0 + c] = __float2half_rn(ts[c][d]);
    }
}

// ============================================================================
// Prep kernels
// ============================================================================
__global__ void split_b_kernel(const float4* __restrict__ q,
                               const float4* __restrict__ k,
                               const float4* __restrict__ v,
                               __half* __restrict__ Ah,
                               __half* __restrict__ Al, int n4) {
    int i = blockIdx.x * blockDim.x + threadIdx.x;
    if (i >= n4) return;
    int z = blockIdx.y;
    const float4* in = (z == 0) ? q : (z == 1) ? k : v;
    __half2* hi = (__half2*)(Ah + (size_t)z * MT * D_MODEL);
    __half2* lo = (__half2*)(Al + (size_t)z * MT * D_MODEL);
    float4 vv = in[i];
    __half2 h01 = __floats2half2_rn(vv.x, vv.y);
    __half2 h23 = __floats2half2_rn(vv.z, vv.w);
    hi[2 * i]     = h01;
    hi[2 * i + 1] = h23;
    float2 f01 = __half22float2(h01), f23 = __half22float2(h23);
    lo[2 * i]     = __floats2half2_rn(vv.x - f01.x, vv.y - f01.y);
    lo[2 * i + 1] = __floats2half2_rn(vv.z - f23.x, vv.w - f23.y);
}

// Weights: hi only (all four) — error analysis shows W-lo passes are below
// the noise floor set by the f16 roundings we already commit to downstream.
__global__ void wt_split_b_kernel(const float* __restrict__ W0,
                                  const float* __restrict__ W1,
                                  const float* __restrict__ W2,
                                  const float* __restrict__ W3,
                                  __half* __restrict__ Wth) {
    __shared__ float ts[32][33];
    int z = blockIdx.z;
    const float* W = (z == 0) ? W0 : (z == 1) ? W1 : (z == 2) ? W2 : W3;
    __half* oh = Wth + (size_t)z * D_MODEL * D_MODEL;
    int n0 = blockIdx.x * 32, k0 = blockIdx.y * 32;
    ts[threadIdx.y][threadIdx.x] = W[(size_t)(k0 + threadIdx.y) * 512 + n0 + threadIdx.x];
    __syncthreads();
    int n = n0 + threadIdx.y, k = k0 + threadIdx.x;
    oh[(size_t)n * 512 + k] = __float2half_rn(ts[threadIdx.x][threadIdx.y]);
}

// ============================================================================
// HMMA GEMM (cp.async double-buffered), f16, f32-acc, uniform 2-pass:
//   Ah·Bh + Al·Bh  (input hi/lo vs weight hi).
// z: 0=Q (pre-scaled by QSCALE, half hi/lo head-split), 1=K (half hi),
// 2=V (f32 head-split), 3=out proj (f32 row-major to d_out).
// ============================================================================
#define GRB    80      // smem row bytes (40 halves)
#define GTILE  10240   // 128 rows
#define GSTAGE 30720   // 3 tiles: Ah, Al, Bh
#define G_SMEM (2 * GSTAGE)

__global__ __launch_bounds__(256, 2) void mm_gemm(
    const __half* __restrict__ Ahb, const __half* __restrict__ Alb,
    const __half* __restrict__ Wthb,
    const float* __restrict__ bq, const float* __restrict__ bk,
    const float* __restrict__ bv, const float* __restrict__ bo,
    __half* __restrict__ Qh, __half* __restrict__ Ql,
    __half* __restrict__ Kh,
    float* __restrict__ Vf, float* __restrict__ dout, int zofs) {
    extern __shared__ __align__(16) char smg[];
    const int tid = threadIdx.x, wid = tid >> 5, lane = tid & 31;
    const int wm = wid >> 1, wn = wid & 1;
    const int gr = lane >> 2, gc = lane & 3;
    const int m0 = blockIdx.y * 128, n0 = blockIdx.x * 128;
    const int z = blockIdx.z + zofs;

    const __half* Ah = Ahb + (size_t)((z == 3) ? 0 : z) * MT * D_MODEL;
    const __half* Al = Alb + (size_t)((z == 3) ? 0 : z) * MT * D_MODEL;
    const __half* Bh = Wthb + (size_t)z * D_MODEL * D_MODEL;
    const float* bias = (z == 0) ? bq : (z == 1) ? bk : (z == 2) ? bv : bo;

    const uint32_t sb = smem_to_u32(smg);
    const uint32_t rAh = (uint32_t)(wm * 32 + (lane & 15)) * GRB + (((lane >> 4) & 1) << 4);
    const uint32_t rBh = 2u * GTILE +
        (uint32_t)(wn * 64 + (lane & 7) + (((lane >> 4) & 1) << 3)) * GRB +
        (((lane >> 3) & 1) << 4);

    const int pr = tid >> 2, pj = tid & 3;
    const uint32_t poff = (uint32_t)pr * GRB + pj * 16;

    float c[2][8][4];
#pragma unroll
    for (int i = 0; i < 2; i++)
#pragma unroll
        for (int j = 0; j < 8; j++)
#pragma unroll
            for (int e = 0; e < 4; e++) c[i][j][e] = 0.0f;

    {
#pragma unroll
        for (int t = 0; t < 2; t++) {
            int r = pr + t * 64;
            uint32_t d = sb + poff + (uint32_t)t * 64 * GRB;
            size_t ga = (size_t)(m0 + r) * 512 + pj * 8;
            size_t gb = (size_t)(n0 + r) * 512 + pj * 8;
            CP16(d, Ah + ga);
            CP16(d + GTILE, Al + ga);
            CP16(d + 2 * GTILE, Bh + gb);
        }
        CP_COMMIT();
    }

    for (int kc = 0; kc < 16; kc++) {
        const uint32_t stg = sb + (uint32_t)(kc & 1) * GSTAGE;
        CP_WAIT0();
        __syncthreads();
        if (kc < 15) {
            const int k0 = (kc + 1) * 32;
            const uint32_t nstg = sb + (uint32_t)((kc + 1) & 1) * GSTAGE;
#pragma unroll
            for (int t = 0; t < 2; t++) {
                int r = pr + t * 64;
                uint32_t d = nstg + poff + (uint32_t)t * 64 * GRB;
                size_t ga = (size_t)(m0 + r) * 512 + k0 + pj * 8;
                size_t gb = (size_t)(n0 + r) * 512 + k0 + pj * 8;
                CP16(d, Ah + ga);
                CP16(d + GTILE, Al + ga);
                CP16(d + 2 * GTILE, Bh + gb);
            }
            CP_COMMIT();
        }

        const uint32_t aAh = stg + rAh, aBh = stg + rBh;
#pragma unroll
        for (int ks = 0; ks < 2; ks++) {
            uint32_t ah[2][4], al[2][4], bfr[4][4];
            ldsm4(ah[0], aAh + ks * 32);
            ldsm4(ah[1], aAh + 16 * GRB + ks * 32);
            ldsm4(al[0], aAh + GTILE + ks * 32);
            ldsm4(al[1], aAh + GTILE + 16 * GRB + ks * 32);
#pragma unroll
            for (int nt2 = 0; nt2 < 4; nt2++)
                ldsm4(bfr[nt2], aBh + nt2 * 16 * GRB + ks * 32);
            // pass 1: Ah*Bh
#pragma unroll
            for (int nt2 = 0; nt2 < 4; nt2++)
#pragma unroll
                for (int q = 0; q < 2; q++)
#pragma unroll
                    for (int mt = 0; mt < 2; mt++)
                        mma_f32h(c[mt][nt2 * 2 + q], ah[mt], &bfr[nt2][q * 2]);
            // pass 2: Al*Bh
#pragma unroll
            for (int nt2 = 0; nt2 < 4; nt2++)
#pragma unroll
                for (int q = 0; q < 2; q++)
#pragma unroll
                    for (int mt = 0; mt < 2; mt++)
                        mma_f32h(c[mt][nt2 * 2 + q], al[mt], &bfr[nt2][q * 2]);
        }
    }

    // Epilogue
#pragma unroll
    for (int mt = 0; mt < 2; mt++) {
#pragma unroll
        for (int half_ = 0; half_ < 2; half_++) {
            int m = m0 + wm * 32 + mt * 16 + gr + half_ * 8;
            int bb = m >> 11, l = m & 2047;
#pragma unroll
            for (int nt = 0; nt < 8; nt++) {
                int n = n0 + wn * 64 + nt * 8 + 2 * gc;
                float v0 = c[mt][nt][half_ * 2 + 0] + bias[n];
                float v1 = c[mt][nt][half_ * 2 + 1] + bias[n + 1];
                if (z == 3) {
                    *(float2*)(dout + (size_t)m * 512 + n) = make_float2(v0, v1);
                } else if (z == 2) {
                    int h = n >> 6, d = n & 63;
                    *(float2*)(Vf + ((size_t)(bb * 8 + h) * SEQ + l) * DK + d) =
                        make_float2(v0, v1);
                } else if (z == 1) {
                    int h = n >> 6, d = n & 63;
                    size_t o = ((size_t)(bb * 8 + h) * SEQ + l) * DK + d;
                    *(__half2*)(Kh + o) = __floats2half2_rn(v0, v1);
                } else {
                    v0 *= QSCALE; v1 *= QSCALE;
                    int h = n >> 6, d = n & 63;
                    size_t o = ((size_t)(bb * 8 + h) * SEQ + l) * DK + d;
                    __half2 hh = __floats2half2_rn(v0, v1);
                    float2 hf = __half22float2(hh);
                    *(__half2*)(Qh + o) = hh;
                    *(__half2*)(Ql + o) = __floats2half2_rn(v0 - hf.x, v1 - hf.y);
                }
            }
        }
    }
}

// ============================================================================
// HMMA flash attention over compacted KV.
// QK = Qh·Kh + Ql·Kh (2-pass); PV = Ph·Vh (1-pass — P-lo below noise floor).
// All f32-acc. 2 CTAs/SM; Q in smem; log2-domain scores; magic exp2.
// ============================================================================
#define ARB   144                 // smem row bytes (72 halves)
#define ATILE (128 * ARB)         // one stage: KH(64 rows) + VH(64 rows)
#define QOFF  (2 * ATILE)         // Q region: QH(128) QL(128)
#define A_SMEM (2 * ATILE + 256 * ARB)   // 73728 bytes

__global__ __launch_bounds__(256, 2) void mm_attn(
    const __half* __restrict__ Qh, const __half* __restrict__ Ql,
    const __half* __restrict__ Kh, const __half* __restrict__ Vh,
    const int* __restrict__ nkp,
    __half* __restrict__ OutH, __half* __restrict__ OutL) {
    extern __shared__ __align__(16) char smA[];

    const int tid = threadIdx.x, wid = tid >> 5, lane = tid & 31;
    const int gr = lane >> 2, gc = lane & 3;
    const int q0 = blockIdx.x * 128;
    const int bh = blockIdx.y, b = bh >> 3, h = bh & 7;
    const int nk = nkp[b];
    const int niter = (nk + 63) >> 6;

    const __half* Qhp = Qh + (size_t)bh * SEQ * DK;
    const __half* Qlp = Ql + (size_t)bh * SEQ * DK;
    const __half* Khp = Kh + (size_t)bh * SEQ * DK;
    const __half* Vhp = Vh + (size_t)bh * DK * SEQ;

    const uint32_t sb = smem_to_u32(smA);
    const int pr = tid >> 3, pj = tid & 7;

    // ---- prefetch KV tile 0 into stage 0 (K rows 0-63, V rows 64-127)
    if (niter > 0) {
#pragma unroll
        for (int t = 0; t < 4; t++) {
            int r = pr + t * 32;
            uint32_t d = sb + (uint32_t)r * ARB + pj * 16;
            if (r < 64)
                CP16(d, Khp + (size_t)r * DK + pj * 8);
            else
                CP16(d, Vhp + (size_t)(r - 64) * SEQ + pj * 8);
        }
        CP_COMMIT();
    }

    // ---- stage Q (persistent region)
#pragma unroll
    for (int t = 0; t < 4; t++) {
        int i = tid + t * 256;
        int r = i >> 3, j = i & 7;
        char* dsth = smA + QOFF + (size_t)r * ARB + j * 16;
        char* dstl = smA + QOFF + (size_t)(128 + r) * ARB + j * 16;
        *(uint4*)dsth = *(const uint4*)(Qhp + (size_t)(q0 + r) * DK + j * 8);
        *(uint4*)dstl = *(const uint4*)(Qlp + (size_t)(q0 + r) * DK + j * 8);
    }
    CP_WAIT0();
    __syncthreads();

    const uint32_t aQb = sb + QOFF +
        (uint32_t)(wid * 16 + (lane & 15)) * ARB + (((lane >> 4) & 1) << 4);
    const uint32_t bro = (uint32_t)((lane & 7) + (((lane >> 4) & 1) << 3)) * ARB +
                         (((lane >> 3) & 1) << 4);

    float m0_ = -1e30f, m1_ = -1e30f, l0_ = 0.0f, l1_ = 0.0f;
    float o[8][4];
#pragma unroll
    for (int j = 0; j < 8; j++)
#pragma unroll
        for (int e = 0; e < 4; e++) o[j][e] = 0.0f;

    for (int it = 0; it < niter; it++) {
        const int cur = it & 1;
        const uint32_t stg = sb + (uint32_t)cur * ATILE;
        const int kt = it * 64;

        if (it + 1 < niter) {
            const int ktn = kt + 64;
            const uint32_t nstg = sb + (uint32_t)(1 - cur) * ATILE;
#pragma unroll
            for (int t = 0; t < 4; t++) {
                int r = pr + t * 32;
                uint32_t d = nstg + (uint32_t)r * ARB + pj * 16;
                if (r < 64)
                    CP16(d, Khp + (size_t)(ktn + r) * DK + pj * 8);
                else
                    CP16(d, Vhp + (size_t)(r - 64) * SEQ + ktn + pj * 8);
            }
            CP_COMMIT();
        }

        // ---- S = Qh·Kh + Ql·Kh (f32 acc; log2 units)
        float s[8][4];
#pragma unroll
        for (int j = 0; j < 8; j++)
#pragma unroll
            for (int e = 0; e < 4; e++) s[j][e] = 0.0f;
        const uint32_t aKh = stg + bro;
#pragma unroll
        for (int ks = 0; ks < 4; ks++) {
            uint32_t qhf[4], qlf[4], kf[4][4];
            ldsm4(qhf, aQb + ks * 32);
            ldsm4(qlf, aQb + 128 * ARB + ks * 32);
#pragma unroll
            for (int nt2 = 0; nt2 < 4; nt2++)
                ldsm4(kf[nt2], aKh + nt2 * 16 * ARB + ks * 32);
#pragma unroll
            for (int nt2 = 0; nt2 < 4; nt2++)
#pragma unroll
                for (int q = 0; q < 2; q++)
                    mma_f32h(s[nt2 * 2 + q], qhf, &kf[nt2][q * 2]);
#pragma unroll
            for (int nt2 = 0; nt2 < 4; nt2++)
#pragma unroll
                for (int q = 0; q < 2; q++)
                    mma_f32h(s[nt2 * 2 + q], qlf, &kf[nt2][q * 2]);
        }

        // ---- tail-tile masking (uniform branch; padded cols K=0 -> s=0)
        if (kt + 64 > nk) {
#pragma unroll
            for (int nt = 0; nt < 8; nt++) {
                int cb = kt + nt * 8 + 2 * gc;
                if (cb >= nk)     { s[nt][0] = -3.0e38f; s[nt][2] = -3.0e38f; }
                if (cb + 1 >= nk) { s[nt][1] = -3.0e38f; s[nt][3] = -3.0e38f; }
            }
        }

        // ---- row max (log2 domain)
        float mx0 = -3.0e38f, mx1 = -3.0e38f;
#pragma unroll
        for (int nt = 0; nt < 8; nt++) {
            mx0 = fmaxf(mx0, fmaxf(s[nt][0], s[nt][1]));
            mx1 = fmaxf(mx1, fmaxf(s[nt][2], s[nt][3]));
        }
        mx0 = fmaxf(mx0, __shfl_xor_sync(0xffffffffu, mx0, 1));
        mx0 = fmaxf(mx0, __shfl_xor_sync(0xffffffffu, mx0, 2));
        mx1 = fmaxf(mx1, __shfl_xor_sync(0xffffffffu, mx1, 1));
        mx1 = fmaxf(mx1, __shfl_xor_sync(0xffffffffu, mx1, 2));
        float mn0 = fmaxf(m0_, mx0), mn1 = fmaxf(m1_, mx1);
        float al0 = fexp2m(m0_ - mn0), al1 = fexp2m(m1_ - mn1);
        m0_ = mn0;
        m1_ = mn1;

        // ---- exp + sums + pack P (hi only) into mma A-fragments
        uint32_t pa_h[4][4];
        float sm0 = 0.0f, sm1 = 0.0f;
#pragma unroll
        for (int nt = 0; nt < 8; nt++) {
            float p0 = fexp2m(s[nt][0] - mn0);
            float p1 = fexp2m(s[nt][1] - mn0);
            float p2 = fexp2m(s[nt][2] - mn1);
            float p3 = fexp2m(s[nt][3] - mn1);
            sm0 += p0 + p1;
            sm1 += p2 + p3;
            int kp = nt >> 1, q = nt & 1;
            __half2 hb01 = __floats2half2_rn(p0, p1);
            __half2 hb23 = __floats2half2_rn(p2, p3);
            pa_h[kp][q * 2 + 0] = *(uint32_t*)&hb01;
            pa_h[kp][q * 2 + 1] = *(uint32_t*)&hb23;
        }
        sm0 += __shfl_xor_sync(0xffffffffu, sm0, 1);
        sm0 += __shfl_xor_sync(0xffffffffu, sm0, 2);
        sm1 += __shfl_xor_sync(0xffffffffu, sm1, 1);
        sm1 += __shfl_xor_sync(0xffffffffu, sm1, 2);
        l0_ = l0_ * al0 + sm0;
        l1_ = l1_ * al1 + sm1;

#pragma unroll
        for (int j = 0; j < 8; j++) {
            o[j][0] *= al0;
            o[j][1] *= al0;
            o[j][2] *= al1;
            o[j][3] *= al1;
        }

        // ---- O += Ph·Vh (f32 acc)
        const uint32_t aVh = stg + 64 * ARB + bro;
#pragma unroll
        for (int kp = 0; kp < 4; kp++) {
            uint32_t vf[4][4];
#pragma unroll
            for (int nt2 = 0; nt2 < 4; nt2++)
                ldsm4(vf[nt2], aVh + nt2 * 16 * ARB + kp * 32);
#pragma unroll
            for (int nt2 = 0; nt2 < 4; nt2++)
#pragma unroll
                for (int q = 0; q < 2; q++)
                    mma_f32h(o[nt2 * 2 + q], pa_h[kp], &vf[nt2][q * 2]);
        }

        if (it + 1 < niter) {
            CP_WAIT0();
            __syncthreads();
        }
    }

    // ---- normalize + store half hi/lo split at (B, L, H*64) for out-proj
    float inv0 = (l0_ > 0.0f) ? 1.0f / l0_ : 0.0f;
    float inv1 = (l1_ > 0.0f) ? 1.0f / l1_ : 0.0f;
    int r0 = q0 + wid * 16 + gr, r1 = r0 + 8;
    size_t base0 = (size_t)(b * SEQ + r0) * D_MODEL + h * DK;
    size_t base1 = (size_t)(b * SEQ + r1) * D_MODEL + h * DK;
#pragma unroll
    for (int nt = 0; nt < 8; nt++) {
        int cl = nt * 8 + 2 * gc;
        float v0 = o[nt][0] * inv0, v1 = o[nt][1] * inv0;
        float v2 = o[nt][2] * inv1, v3 = o[nt][3] * inv1;
        __half2 h01 = __floats2half2_rn(v0, v1);
        __half2 h23 = __floats2half2_rn(v2, v3);
        float2 f01 = __half22float2(h01), f23 = __half22float2(h23);
        *(__half2*)(OutH + base0 + cl) = h01;
        *(__half2*)(OutL + base0 + cl) = __floats2half2_rn(v0 - f01.x, v1 - f01.y);
        *(__half2*)(OutH + base1 + cl) = h23;
        *(__half2*)(OutL + base1 + cl) = __floats2half2_rn(v2 - f23.x, v3 - f23.y);
    }
}

// ============================================================================
// Launch: 7 kernels total
// ============================================================================
extern "C" void kernel_launch(void* const* d_in, const int* in_sizes, int n_in,
                              void* d_out, int out_size) {
    const float* query = (const float*)d_in[0];
    const float* key   = (const float*)d_in[1];
    const float* value = (const float*)d_in[2];
    const int*   mask  = (const int*)d_in[3];
    const float* Wq = (const float*)d_in[4];
    const float* bq = (const float*)d_in[5];
    const float* Wk = (const float*)d_in[6];
    const float* bk = (const float*)d_in[7];
    const float* Wv = (const float*)d_in[8];
    const float* bv = (const float*)d_in[9];
    const float* Wo = (const float*)d_in[10];
    const float* bo = (const float*)d_in[11];

    __half *Ah, *Al, *Wth, *Qh, *Ql, *Kh, *Khc, *Vth;
    float *Vf;
    int *idx, *nk;
    cudaGetSymbolAddress((void**)&Ah, g_Ah);
    cudaGetSymbolAddress((void**)&Al, g_Al);
    cudaGetSymbolAddress((void**)&Wth, g_Wth);
    cudaGetSymbolAddress((void**)&Qh, g_Qh);
    cudaGetSymbolAddress((void**)&Ql, g_Ql);
    cudaGetSymbolAddress((void**)&Kh, g_Kh);
    cudaGetSymbolAddress((void**)&Khc, g_Khc);
    cudaGetSymbolAddress((void**)&Vf, g_Vf);
    cudaGetSymbolAddress((void**)&Vth, g_Vth);
    cudaGetSymbolAddress((void**)&idx, g_idx);
    cudaGetSymbolAddress((void**)&nk, g_nk);

    cudaFuncSetAttribute(mm_gemm, cudaFuncAttributeMaxDynamicSharedMemorySize,
                         G_SMEM);
    cudaFuncSetAttribute(mm_attn, cudaFuncAttributeMaxDynamicSharedMemorySize,
                         A_SMEM);

    const int N4 = MT * D_MODEL / 4;

    mask_scan_kernel<<<BATCH, 1024>>>(mask, idx, nk);
    wt_split_b_kernel<<<dim3(16, 16, 4), dim3(32, 32)>>>(Wq, Wk, Wv, Wo, Wth);
    split_b_kernel<<<dim3(N4 / 256, 3), 256>>>((const float4*)query,
                                               (const float4*)key,
                                               (const float4*)value, Ah, Al, N4);
    mm_gemm<<<dim3(4, 64, 3), 256, G_SMEM>>>(Ah, Al, Wth, bq, bk, bv, bo,
                                             Qh, Ql, Kh, Vf, nullptr, 0);
    kv_gather_kernel<<<dim3(SEQ / 64, BH), 256>>>(Kh, Vf, idx, nk, Khc, Vth);
    mm_attn<<<dim3(SEQ / 128, BH), 256, A_SMEM>>>(Qh, Ql, Khc, Vth, nk, Ah, Al);
    mm_gemm<<<dim3(4, 64, 1), 256, G_SMEM>>>(Ah, Al, Wth, bq, bk, bv, bo,
                                             nullptr, nullptr, nullptr, nullptr,
                                             (float*)d_out, 3);
}

// round 14
// speedup vs baseline: 2.2137x; 1.3282x over previous
#include <cuda_runtime.h>
#include <cuda_fp16.h>
#include <cstdint>

#define NUM_HEADS 8
#define D_MODEL   512
#define DK        64
#define SEQ       2048
#define BATCH     4
#define MT        (BATCH * SEQ)        // 8192
#define BH        (BATCH * NUM_HEADS)  // 32

// ============================================================================
// Scratch (device globals — no allocation allowed)
// ============================================================================
__device__ __align__(16) __half g_Ah[3 * MT * D_MODEL];
__device__ __align__(16) __half g_Wth[4 * D_MODEL * D_MODEL];
__device__ __align__(16) __half g_Qh[BH * SEQ * DK];
__device__ __align__(16) __half g_Kh[BH * SEQ * DK];
__device__ __align__(16) __half g_Khc[BH * SEQ * DK];  // compacted K
__device__ __align__(16) float  g_Vf[BH * SEQ * DK];
__device__ __align__(16) __half g_Vth[BH * DK * SEQ];  // compacted V^T
__device__ int g_idx[BATCH * SEQ];
__device__ int g_nk[BATCH];

// 0.125 (1/sqrt(d_k)) * log2(e): folded into Q projection so S is in log2 units
#define QSCALE 0.18033688011117128f

// ============================================================================
// PTX primitives (all legal at compute_103 baseline)
// ============================================================================
__device__ __forceinline__ uint32_t smem_to_u32(const void* p) {
    uint32_t a;
    asm("{ .reg .u64 t; cvta.to.shared.u64 t, %1; cvt.u32.u64 %0, t; }"
        : "=r"(a) : "l"(p));
    return a;
}

__device__ __forceinline__ void ldsm4(uint32_t* r, uint32_t addr) {
    asm volatile("ldmatrix.sync.aligned.m8n8.x4.shared.b16 {%0,%1,%2,%3}, [%4];"
                 : "=r"(r[0]), "=r"(r[1]), "=r"(r[2]), "=r"(r[3]) : "r"(addr));
}

// f16 inputs, f32 accumulate
__device__ __forceinline__ void mma_f32h(float* c, const uint32_t* a,
                                         const uint32_t* b) {
    asm volatile(
        "mma.sync.aligned.m16n8k16.row.col.f32.f16.f16.f32 "
        "{%0,%1,%2,%3}, {%4,%5,%6,%7}, {%8,%9}, {%0,%1,%2,%3};"
        : "+f"(c[0]), "+f"(c[1]), "+f"(c[2]), "+f"(c[3])
        : "r"(a[0]), "r"(a[1]), "r"(a[2]), "r"(a[3]), "r"(b[0]), "r"(b[1]));
}

#define CP16(dst, src) \
    asm volatile("cp.async.cg.shared.global [%0], [%1], 16;" \
                 :: "r"(dst), "l"(src) : "memory")
#define CP_COMMIT() asm volatile("cp.async.commit_group;" ::: "memory")
#define CP_WAIT0()  asm volatile("cp.async.wait_group 0;" ::: "memory")

// exp2 via magic-constant round + degree-4 poly on [-0.5, 0.5]; t <= 0.
__device__ __forceinline__ float fexp2m(float t) {
    t = fmaxf(t, -126.0f);
    float z = t + 12582912.0f;
    float f = t - (z - 12582912.0f);
    float p = fmaf(f, 0.0096181291f, 0.0555041087f);
    p = fmaf(p, f, 0.2402265069f);
    p = fmaf(p, f, 0.6931471806f);
    p = fmaf(p, f, 1.0f);
    uint32_t sb = (uint32_t)((__float_as_int(z) + 127) << 23);
    return __int_as_float(sb) * p;
}

// ============================================================================
// Mask prefix scan
// ============================================================================
__global__ __launch_bounds__(1024) void mask_scan_kernel(
    const int* __restrict__ mask, int* __restrict__ idx, int* __restrict__ nk) {
    const int b = blockIdx.x, tid = threadIdx.x;
    const int lane = tid & 31, w = tid >> 5;
    const int* mp = mask + b * SEQ;
    int e0 = (mp[2 * tid] != 0), e1 = (mp[2 * tid + 1] != 0);
    int tsum = e0 + e1;
    int v = tsum;
#pragma unroll
    for (int o = 1; o < 32; o <<= 1) {
        int u = __shfl_up_sync(0xffffffffu, v, o);
        if (lane >= o) v += u;
    }
    __shared__ int ws[32];
    if (lane == 31) ws[w] = v;
    __syncthreads();
    if (w == 0) {
        int x = ws[lane];
#pragma unroll
        for (int o = 1; o < 32; o <<= 1) {
            int u = __shfl_up_sync(0xffffffffu, x, o);
            if (lane >= o) x += u;
        }
        ws[lane] = x;
    }
    __syncthreads();
    int base = ((w > 0) ? ws[w - 1] : 0) + (v - tsum);
    if (e0) idx[b * SEQ + base] = 2 * tid;
    if (e1) idx[b * SEQ + base + e0] = 2 * tid + 1;
    if (tid == 0) nk[b] = ws[31];
}

// ============================================================================
// KV gather: pack unmasked K rows densely; gather+transpose V.
// ============================================================================
__global__ __launch_bounds__(256) void kv_gather_kernel(
    const __half* __restrict__ Kh, const float* __restrict__ Vf,
    const int* __restrict__ idx, const int* __restrict__ nk,
    __half* __restrict__ Khc, __half* __restrict__ Vth) {
    const int t = blockIdx.x, bh = blockIdx.y, b = bh >> 3;
    const int tid = threadIdx.x;
    const int n = nk[b];
    const int j0 = t * 64;
    if (j0 >= ((n + 63) & ~63)) return;
    const int* idxb = idx + b * SEQ;

    const uint4 z4 = make_uint4(0, 0, 0, 0);
#pragma unroll
    for (int t2 = 0; t2 < 2; t2++) {
        int i = tid + t2 * 256;
        int r = i >> 3, j = i & 7;
        int jj = j0 + r;
        int row = (jj < n) ? idxb[jj] : -1;
        size_t src = ((size_t)bh * SEQ + row) * DK + j * 8;
        size_t dst = ((size_t)bh * SEQ + jj) * DK + j * 8;
        *(uint4*)(Khc + dst) = (row >= 0) ? *(const uint4*)(Kh + src) : z4;
    }

    __shared__ float ts[64][65];
    for (int i = tid; i < 4096; i += 256) {
        int r = i >> 6, c = i & 63;
        int jj = j0 + r;
        int row = (jj < n) ? idxb[jj] : -1;
        ts[r][c] = (row >= 0) ? Vf[((size_t)bh * SEQ + row) * DK + c] : 0.0f;
    }
    __syncthreads();
    for (int i = tid; i < 4096; i += 256) {
        int d = i >> 6, c = i & 63;
        Vth[((size_t)bh * DK + d) * SEQ + j0 + c] = __float2half_rn(ts[c][d]);
    }
}

// ============================================================================
// Prep kernels
// ============================================================================
__global__ void conv_b_kernel(const float4* __restrict__ q,
                              const float4* __restrict__ k,
                              const float4* __restrict__ v,
                              __half* __restrict__ Ah, int n4) {
    int i = blockIdx.x * blockDim.x + threadIdx.x;
    if (i >= n4) return;
    int z = blockIdx.y;
    const float4* in = (z == 0) ? q : (z == 1) ? k : v;
    __half2* hi = (__half2*)(Ah + (size_t)z * MT * D_MODEL);
    float4 vv = in[i];
    hi[2 * i]     = __floats2half2_rn(vv.x, vv.y);
    hi[2 * i + 1] = __floats2half2_rn(vv.z, vv.w);
}

__global__ void wt_split_b_kernel(const float* __restrict__ W0,
                                  const float* __restrict__ W1,
                                  const float* __restrict__ W2,
                                  const float* __restrict__ W3,
                                  __half* __restrict__ Wth) {
    __shared__ float ts[32][33];
    int z = blockIdx.z;
    const float* W = (z == 0) ? W0 : (z == 1) ? W1 : (z == 2) ? W2 : W3;
    __half* oh = Wth + (size_t)z * D_MODEL * D_MODEL;
    int n0 = blockIdx.x * 32, k0 = blockIdx.y * 32;
    ts[threadIdx.y][threadIdx.x] = W[(size_t)(k0 + threadIdx.y) * 512 + n0 + threadIdx.x];
    __syncthreads();
    int n = n0 + threadIdx.y, k = k0 + threadIdx.x;
    oh[(size_t)n * 512 + k] = __float2half_rn(ts[threadIdx.x][threadIdx.y]);
}

// ============================================================================
// HMMA GEMM (cp.async double-buffered), f16, f32-acc, single pass: Ah·Bh.
// z: 0=Q (pre-scaled by QSCALE, f16 head-split), 1=K (f16 head-split),
// 2=V (f32 head-split), 3=out proj (f32 row-major to d_out).
// ============================================================================
#define GRB    80      // smem row bytes (40 halves)
#define GTILE  10240   // 128 rows
#define GSTAGE 20480   // 2 tiles: Ah, Bh
#define G_SMEM (2 * GSTAGE)

__global__ __launch_bounds__(256, 2) void mm_gemm(
    const __half* __restrict__ Ahb, const __half* __restrict__ Wthb,
    const float* __restrict__ bq, const float* __restrict__ bk,
    const float* __restrict__ bv, const float* __restrict__ bo,
    __half* __restrict__ Qh, __half* __restrict__ Kh,
    float* __restrict__ Vf, float* __restrict__ dout, int zofs) {
    extern __shared__ __align__(16) char smg[];
    const int tid = threadIdx.x, wid = tid >> 5, lane = tid & 31;
    const int wm = wid >> 1, wn = wid & 1;
    const int gr = lane >> 2, gc = lane & 3;
    const int m0 = blockIdx.y * 128, n0 = blockIdx.x * 128;
    const int z = blockIdx.z + zofs;

    const __half* Ah = Ahb + (size_t)((z == 3) ? 0 : z) * MT * D_MODEL;
    const __half* Bh = Wthb + (size_t)z * D_MODEL * D_MODEL;
    const float* bias = (z == 0) ? bq : (z == 1) ? bk : (z == 2) ? bv : bo;

    const uint32_t sb = smem_to_u32(smg);
    const uint32_t rAh = (uint32_t)(wm * 32 + (lane & 15)) * GRB + (((lane >> 4) & 1) << 4);
    const uint32_t rBh = GTILE +
        (uint32_t)(wn * 64 + (lane & 7) + (((lane >> 4) & 1) << 3)) * GRB +
        (((lane >> 3) & 1) << 4);

    const int pr = tid >> 2, pj = tid & 3;
    const uint32_t poff = (uint32_t)pr * GRB + pj * 16;

    float c[2][8][4];
#pragma unroll
    for (int i = 0; i < 2; i++)
#pragma unroll
        for (int j = 0; j < 8; j++)
#pragma unroll
            for (int e = 0; e < 4; e++) c[i][j][e] = 0.0f;

    {
#pragma unroll
        for (int t = 0; t < 2; t++) {
            int r = pr + t * 64;
            uint32_t d = sb + poff + (uint32_t)t * 64 * GRB;
            CP16(d, Ah + (size_t)(m0 + r) * 512 + pj * 8);
            CP16(d + GTILE, Bh + (size_t)(n0 + r) * 512 + pj * 8);
        }
        CP_COMMIT();
    }

    for (int kc = 0; kc < 16; kc++) {
        const uint32_t stg = sb + (uint32_t)(kc & 1) * GSTAGE;
        CP_WAIT0();
        __syncthreads();
        if (kc < 15) {
            const int k0 = (kc + 1) * 32;
            const uint32_t nstg = sb + (uint32_t)((kc + 1) & 1) * GSTAGE;
#pragma unroll
            for (int t = 0; t < 2; t++) {
                int r = pr + t * 64;
                uint32_t d = nstg + poff + (uint32_t)t * 64 * GRB;
                CP16(d, Ah + (size_t)(m0 + r) * 512 + k0 + pj * 8);
                CP16(d + GTILE, Bh + (size_t)(n0 + r) * 512 + k0 + pj * 8);
            }
            CP_COMMIT();
        }

        const uint32_t aAh = stg + rAh, aBh = stg + rBh;
#pragma unroll
        for (int ks = 0; ks < 2; ks++) {
            uint32_t ah[2][4], bfr[4][4];
            ldsm4(ah[0], aAh + ks * 32);
            ldsm4(ah[1], aAh + 16 * GRB + ks * 32);
#pragma unroll
            for (int nt2 = 0; nt2 < 4; nt2++)
                ldsm4(bfr[nt2], aBh + nt2 * 16 * GRB + ks * 32);
#pragma unroll
            for (int nt2 = 0; nt2 < 4; nt2++)
#pragma unroll
                for (int q = 0; q < 2; q++)
#pragma unroll
                    for (int mt = 0; mt < 2; mt++)
                        mma_f32h(c[mt][nt2 * 2 + q], ah[mt], &bfr[nt2][q * 2]);
        }
    }

    // Epilogue
#pragma unroll
    for (int mt = 0; mt < 2; mt++) {
#pragma unroll
        for (int half_ = 0; half_ < 2; half_++) {
            int m = m0 + wm * 32 + mt * 16 + gr + half_ * 8;
            int bb = m >> 11, l = m & 2047;
#pragma unroll
            for (int nt = 0; nt < 8; nt++) {
                int n = n0 + wn * 64 + nt * 8 + 2 * gc;
                float v0 = c[mt][nt][half_ * 2 + 0] + bias[n];
                float v1 = c[mt][nt][half_ * 2 + 1] + bias[n + 1];
                if (z == 3) {
                    *(float2*)(dout + (size_t)m * 512 + n) = make_float2(v0, v1);
                } else if (z == 2) {
                    int h = n >> 6, d = n & 63;
                    *(float2*)(Vf + ((size_t)(bb * 8 + h) * SEQ + l) * DK + d) =
                        make_float2(v0, v1);
                } else {
                    if (z == 0) { v0 *= QSCALE; v1 *= QSCALE; }
                    int h = n >> 6, d = n & 63;
                    size_t o = ((size_t)(bb * 8 + h) * SEQ + l) * DK + d;
                    __half* oh = (z == 0) ? Qh : Kh;
                    *(__half2*)(oh + o) = __floats2half2_rn(v0, v1);
                }
            }
        }
    }
}

// ============================================================================
// HMMA flash attention over compacted KV, pure f16 single-pass matmuls.
// QK = Qh·Kh; PV = Ph·Vh. All f32-acc. 2 CTAs/SM; Q in smem;
// log2-domain scores; magic exp2; clamp masking.
// ============================================================================
#define ARB   144                 // smem row bytes (72 halves)
#define ATILE (128 * ARB)         // one stage: KH(64 rows) + VH(64 rows)
#define QOFF  (2 * ATILE)         // Q region: QH(128 rows)
#define A_SMEM (2 * ATILE + 128 * ARB)   // 55296 bytes

__global__ __launch_bounds__(256, 2) void mm_attn(
    const __half* __restrict__ Qh,
    const __half* __restrict__ Kh, const __half* __restrict__ Vh,
    const int* __restrict__ nkp, __half* __restrict__ OutH) {
    extern __shared__ __align__(16) char smA[];

    const int tid = threadIdx.x, wid = tid >> 5, lane = tid & 31;
    const int gr = lane >> 2, gc = lane & 3;
    const int q0 = blockIdx.x * 128;
    const int bh = blockIdx.y, b = bh >> 3, h = bh & 7;
    const int nk = nkp[b];
    const int niter = (nk + 63) >> 6;

    const __half* Qhp = Qh + (size_t)bh * SEQ * DK;
    const __half* Khp = Kh + (size_t)bh * SEQ * DK;
    const __half* Vhp = Vh + (size_t)bh * DK * SEQ;

    const uint32_t sb = smem_to_u32(smA);
    const int pr = tid >> 3, pj = tid & 7;

    // ---- prefetch KV tile 0 into stage 0 (K rows 0-63, V rows 64-127)
    if (niter > 0) {
#pragma unroll
        for (int t = 0; t < 4; t++) {
            int r = pr + t * 32;
            uint32_t d = sb + (uint32_t)r * ARB + pj * 16;
            if (r < 64)
                CP16(d, Khp + (size_t)r * DK + pj * 8);
            else
                CP16(d, Vhp + (size_t)(r - 64) * SEQ + pj * 8);
        }
        CP_COMMIT();
    }

    // ---- stage Q (persistent region)
#pragma unroll
    for (int t = 0; t < 2; t++) {
        int i = tid + t * 256;
        int r = i >> 2, j = i & 3;
        char* dst = smA + QOFF + (size_t)r * ARB + j * 32;
        const __half* src = Qhp + (size_t)(q0 + r) * DK + j * 16;
        *(uint4*)dst = *(const uint4*)src;
        *(uint4*)(dst + 16) = *(const uint4*)(src + 8);
    }
    CP_WAIT0();
    __syncthreads();

    const uint32_t aQb = sb + QOFF +
        (uint32_t)(wid * 16 + (lane & 15)) * ARB + (((lane >> 4) & 1) << 4);
    const uint32_t bro = (uint32_t)((lane & 7) + (((lane >> 4) & 1) << 3)) * ARB +
                         (((lane >> 3) & 1) << 4);

    float m0_ = -1e30f, m1_ = -1e30f, l0_ = 0.0f, l1_ = 0.0f;
    float o[8][4];
#pragma unroll
    for (int j = 0; j < 8; j++)
#pragma unroll
        for (int e = 0; e < 4; e++) o[j][e] = 0.0f;

    for (int it = 0; it < niter; it++) {
        const int cur = it & 1;
        const uint32_t stg = sb + (uint32_t)cur * ATILE;
        const int kt = it * 64;

        if (it + 1 < niter) {
            const int ktn = kt + 64;
            const uint32_t nstg = sb + (uint32_t)(1 - cur) * ATILE;
#pragma unroll
            for (int t = 0; t < 4; t++) {
                int r = pr + t * 32;
                uint32_t d = nstg + (uint32_t)r * ARB + pj * 16;
                if (r < 64)
                    CP16(d, Khp + (size_t)(ktn + r) * DK + pj * 8);
                else
                    CP16(d, Vhp + (size_t)(r - 64) * SEQ + ktn + pj * 8);
            }
            CP_COMMIT();
        }

        // ---- S = Qh·Kh (f32 acc; log2 units)
        float s[8][4];
#pragma unroll
        for (int j = 0; j < 8; j++)
#pragma unroll
            for (int e = 0; e < 4; e++) s[j][e] = 0.0f;
        const uint32_t aKh = stg + bro;
#pragma unroll
        for (int ks = 0; ks < 4; ks++) {
            uint32_t qhf[4], kf[4][4];
            ldsm4(qhf, aQb + ks * 32);
#pragma unroll
            for (int nt2 = 0; nt2 < 4; nt2++)
                ldsm4(kf[nt2], aKh + nt2 * 16 * ARB + ks * 32);
#pragma unroll
            for (int nt2 = 0; nt2 < 4; nt2++)
#pragma unroll
                for (int q = 0; q < 2; q++)
                    mma_f32h(s[nt2 * 2 + q], qhf, &kf[nt2][q * 2]);
        }

        // ---- tail-tile masking (uniform branch; padded cols K=0 -> s=0)
        if (kt + 64 > nk) {
#pragma unroll
            for (int nt = 0; nt < 8; nt++) {
                int cb = kt + nt * 8 + 2 * gc;
                if (cb >= nk)     { s[nt][0] = -3.0e38f; s[nt][2] = -3.0e38f; }
                if (cb + 1 >= nk) { s[nt][1] = -3.0e38f; s[nt][3] = -3.0e38f; }
            }
        }

        // ---- row max (log2 domain)
        float mx0 = -3.0e38f, mx1 = -3.0e38f;
#pragma unroll
        for (int nt = 0; nt < 8; nt++) {
            mx0 = fmaxf(mx0, fmaxf(s[nt][0], s[nt][1]));
            mx1 = fmaxf(mx1, fmaxf(s[nt][2], s[nt][3]));
        }
        mx0 = fmaxf(mx0, __shfl_xor_sync(0xffffffffu, mx0, 1));
        mx0 = fmaxf(mx0, __shfl_xor_sync(0xffffffffu, mx0, 2));
        mx1 = fmaxf(mx1, __shfl_xor_sync(0xffffffffu, mx1, 1));
        mx1 = fmaxf(mx1, __shfl_xor_sync(0xffffffffu, mx1, 2));
        float mn0 = fmaxf(m0_, mx0), mn1 = fmaxf(m1_, mx1);
        float al0 = fexp2m(m0_ - mn0), al1 = fexp2m(m1_ - mn1);
        m0_ = mn0;
        m1_ = mn1;

        // ---- exp + sums + pack P into mma A-fragments
        uint32_t pa_h[4][4];
        float sm0 = 0.0f, sm1 = 0.0f;
#pragma unroll
        for (int nt = 0; nt < 8; nt++) {
            float p0 = fexp2m(s[nt][0] - mn0);
            float p1 = fexp2m(s[nt][1] - mn0);
            float p2 = fexp2m(s[nt][2] - mn1);
            float p3 = fexp2m(s[nt][3] - mn1);
            sm0 += p0 + p1;
            sm1 += p2 + p3;
            int kp = nt >> 1, q = nt & 1;
            __half2 hb01 = __floats2half2_rn(p0, p1);
            __half2 hb23 = __floats2half2_rn(p2, p3);
            pa_h[kp][q * 2 + 0] = *(uint32_t*)&hb01;
            pa_h[kp][q * 2 + 1] = *(uint32_t*)&hb23;
        }
        sm0 += __shfl_xor_sync(0xffffffffu, sm0, 1);
        sm0 += __shfl_xor_sync(0xffffffffu, sm0, 2);
        sm1 += __shfl_xor_sync(0xffffffffu, sm1, 1);
        sm1 += __shfl_xor_sync(0xffffffffu, sm1, 2);
        l0_ = l0_ * al0 + sm0;
        l1_ = l1_ * al1 + sm1;

#pragma unroll
        for (int j = 0; j < 8; j++) {
            o[j][0] *= al0;
            o[j][1] *= al0;
            o[j][2] *= al1;
            o[j][3] *= al1;
        }

        // ---- O += Ph·Vh (f32 acc)
        const uint32_t aVh = stg + 64 * ARB + bro;
#pragma unroll
        for (int kp = 0; kp < 4; kp++) {
            uint32_t vf[4][4];
#pragma unroll
            for (int nt2 = 0; nt2 < 4; nt2++)
                ldsm4(vf[nt2], aVh + nt2 * 16 * ARB + kp * 32);
#pragma unroll
            for (int nt2 = 0; nt2 < 4; nt2++)
#pragma unroll
                for (int q = 0; q < 2; q++)
                    mma_f32h(o[nt2 * 2 + q], pa_h[kp], &vf[nt2][q * 2]);
        }

        if (it + 1 < niter) {
            CP_WAIT0();
            __syncthreads();
        }
    }

    // ---- normalize + store f16 at (B, L, H*64) for out-proj
    float inv0 = (l0_ > 0.0f) ? 1.0f / l0_ : 0.0f;
    float inv1 = (l1_ > 0.0f) ? 1.0f / l1_ : 0.0f;
    int r0 = q0 + wid * 16 + gr, r1 = r0 + 8;
    size_t base0 = (size_t)(b * SEQ + r0) * D_MODEL + h * DK;
    size_t base1 = (size_t)(b * SEQ + r1) * D_MODEL + h * DK;
#pragma unroll
    for (int nt = 0; nt < 8; nt++) {
        int cl = nt * 8 + 2 * gc;
        *(__half2*)(OutH + base0 + cl) =
            __floats2half2_rn(o[nt][0] * inv0, o[nt][1] * inv0);
        *(__half2*)(OutH + base1 + cl) =
            __floats2half2_rn(o[nt][2] * inv1, o[nt][3] * inv1);
    }
}

// ============================================================================
// Launch: 7 kernels total
// ============================================================================
extern "C" void kernel_launch(void* const* d_in, const int* in_sizes, int n_in,
                              void* d_out, int out_size) {
    const float* query = (const float*)d_in[0];
    const float* key   = (const float*)d_in[1];
    const float* value = (const float*)d_in[2];
    const int*   mask  = (const int*)d_in[3];
    const float* Wq = (const float*)d_in[4];
    const float* bq = (const float*)d_in[5];
    const float* Wk = (const float*)d_in[6];
    const float* bk = (const float*)d_in[7];
    const float* Wv = (const float*)d_in[8];
    const float* bv = (const float*)d_in[9];
    const float* Wo = (const float*)d_in[10];
    const float* bo = (const float*)d_in[11];

    __half *Ah, *Wth, *Qh, *Kh, *Khc, *Vth;
    float *Vf;
    int *idx, *nk;
    cudaGetSymbolAddress((void**)&Ah, g_Ah);
    cudaGetSymbolAddress((void**)&Wth, g_Wth);
    cudaGetSymbolAddress((void**)&Qh, g_Qh);
    cudaGetSymbolAddress((void**)&Kh, g_Kh);
    cudaGetSymbolAddress((void**)&Khc, g_Khc);
    cudaGetSymbolAddress((void**)&Vf, g_Vf);
    cudaGetSymbolAddress((void**)&Vth, g_Vth);
    cudaGetSymbolAddress((void**)&idx, g_idx);
    cudaGetSymbolAddress((void**)&nk, g_nk);

    cudaFuncSetAttribute(mm_gemm, cudaFuncAttributeMaxDynamicSharedMemorySize,
                         G_SMEM);
    cudaFuncSetAttribute(mm_attn, cudaFuncAttributeMaxDynamicSharedMemorySize,
                         A_SMEM);

    const int N4 = MT * D_MODEL / 4;

    mask_scan_kernel<<<BATCH, 1024>>>(mask, idx, nk);
    wt_split_b_kernel<<<dim3(16, 16, 4), dim3(32, 32)>>>(Wq, Wk, Wv, Wo, Wth);
    conv_b_kernel<<<dim3(N4 / 256, 3), 256>>>((const float4*)query,
                                              (const float4*)key,
                                              (const float4*)value, Ah, N4);
    mm_gemm<<<dim3(4, 64, 3), 256, G_SMEM>>>(Ah, Wth, bq, bk, bv, bo,
                                             Qh, Kh, Vf, nullptr, 0);
    kv_gather_kernel<<<dim3(SEQ / 64, BH), 256>>>(Kh, Vf, idx, nk, Khc, Vth);
    mm_attn<<<dim3(SEQ / 128, BH), 256, A_SMEM>>>(Qh, Khc, Vth, nk, Ah);
    mm_gemm<<<dim3(4, 64, 1), 256, G_SMEM>>>(Ah, Wth, bq, bk, bv, bo,
                                             nullptr, nullptr, nullptr,
                                             (float*)d_out, 3);
}

// round 15
// speedup vs baseline: 2.2435x; 1.0135x over previous
#include <cuda_runtime.h>
#include <cuda_fp16.h>
#include <cstdint>

#define NUM_HEADS 8
#define D_MODEL   512
#define DK        64
#define SEQ       2048
#define BATCH     4
#define MT        (BATCH * SEQ)        // 8192
#define BH        (BATCH * NUM_HEADS)  // 32

// ============================================================================
// Scratch (device globals — no allocation allowed)
// ============================================================================
__device__ __align__(16) __half g_Ah[3 * MT * D_MODEL];
__device__ __align__(16) __half g_Wth[4 * D_MODEL * D_MODEL];
__device__ __align__(16) __half g_Qh[BH * SEQ * DK];
__device__ __align__(16) __half g_Kh[BH * SEQ * DK];
__device__ __align__(16) float  g_Vf[BH * SEQ * DK];
__device__ __align__(16) __half g_Vth[BH * DK * SEQ];  // compacted V^T
__device__ int g_idx[BATCH * SEQ];
__device__ int g_nk[BATCH];

// 0.125 (1/sqrt(d_k)) * log2(e): folded into Q projection so S is in log2 units
#define QSCALE 0.18033688011117128f

// ============================================================================
// PTX primitives (all legal at compute_103 baseline)
// ============================================================================
__device__ __forceinline__ uint32_t smem_to_u32(const void* p) {
    uint32_t a;
    asm("{ .reg .u64 t; cvta.to.shared.u64 t, %1; cvt.u32.u64 %0, t; }"
        : "=r"(a) : "l"(p));
    return a;
}

__device__ __forceinline__ void ldsm4(uint32_t* r, uint32_t addr) {
    asm volatile("ldmatrix.sync.aligned.m8n8.x4.shared.b16 {%0,%1,%2,%3}, [%4];"
                 : "=r"(r[0]), "=r"(r[1]), "=r"(r[2]), "=r"(r[3]) : "r"(addr));
}

// f16 inputs, f32 accumulate
__device__ __forceinline__ void mma_f32h(float* c, const uint32_t* a,
                                         const uint32_t* b) {
    asm volatile(
        "mma.sync.aligned.m16n8k16.row.col.f32.f16.f16.f32 "
        "{%0,%1,%2,%3}, {%4,%5,%6,%7}, {%8,%9}, {%0,%1,%2,%3};"
        : "+f"(c[0]), "+f"(c[1]), "+f"(c[2]), "+f"(c[3])
        : "r"(a[0]), "r"(a[1]), "r"(a[2]), "r"(a[3]), "r"(b[0]), "r"(b[1]));
}

#define CP16(dst, src) \
    asm volatile("cp.async.cg.shared.global [%0], [%1], 16;" \
                 :: "r"(dst), "l"(src) : "memory")
#define CP_COMMIT() asm volatile("cp.async.commit_group;" ::: "memory")
#define CP_WAIT0()  asm volatile("cp.async.wait_group 0;" ::: "memory")

// exp2 via magic-constant round + degree-4 poly on [-0.5, 0.5]; t <= 0.
__device__ __forceinline__ float fexp2m(float t) {
    t = fmaxf(t, -126.0f);
    float z = t + 12582912.0f;
    float f = t - (z - 12582912.0f);
    float p = fmaf(f, 0.0096181291f, 0.0555041087f);
    p = fmaf(p, f, 0.2402265069f);
    p = fmaf(p, f, 0.6931471806f);
    p = fmaf(p, f, 1.0f);
    uint32_t sb = (uint32_t)((__float_as_int(z) + 127) << 23);
    return __int_as_float(sb) * p;
}

// ============================================================================
// Mask prefix scan
// ============================================================================
__global__ __launch_bounds__(1024) void mask_scan_kernel(
    const int* __restrict__ mask, int* __restrict__ idx, int* __restrict__ nk) {
    const int b = blockIdx.x, tid = threadIdx.x;
    const int lane = tid & 31, w = tid >> 5;
    const int* mp = mask + b * SEQ;
    int e0 = (mp[2 * tid] != 0), e1 = (mp[2 * tid + 1] != 0);
    int tsum = e0 + e1;
    int v = tsum;
#pragma unroll
    for (int o = 1; o < 32; o <<= 1) {
        int u = __shfl_up_sync(0xffffffffu, v, o);
        if (lane >= o) v += u;
    }
    __shared__ int ws[32];
    if (lane == 31) ws[w] = v;
    __syncthreads();
    if (w == 0) {
        int x = ws[lane];
#pragma unroll
        for (int o = 1; o < 32; o <<= 1) {
            int u = __shfl_up_sync(0xffffffffu, x, o);
            if (lane >= o) x += u;
        }
        ws[lane] = x;
    }
    __syncthreads();
    int base = ((w > 0) ? ws[w - 1] : 0) + (v - tsum);
    if (e0) idx[b * SEQ + base] = 2 * tid;
    if (e1) idx[b * SEQ + base + e0] = 2 * tid + 1;
    if (tid == 0) nk[b] = ws[31];
}

// ============================================================================
// V gather: gather unmasked V rows + transpose + f16 convert.
// (K is consumed via indirect loads inside attention — no K compaction pass.)
// ============================================================================
__global__ __launch_bounds__(256) void v_gather_kernel(
    const float* __restrict__ Vf, const int* __restrict__ idx,
    const int* __restrict__ nk, __half* __restrict__ Vth) {
    const int t = blockIdx.x, bh = blockIdx.y, b = bh >> 3;
    const int tid = threadIdx.x;
    const int n = nk[b];
    const int j0 = t * 64;
    if (j0 >= ((n + 63) & ~63)) return;
    const int* idxb = idx + b * SEQ;

    __shared__ float ts[64][65];
    for (int i = tid; i < 4096; i += 256) {
        int r = i >> 6, c = i & 63;
        int jj = j0 + r;
        int row = (jj < n) ? idxb[jj] : -1;
        ts[r][c] = (row >= 0) ? Vf[((size_t)bh * SEQ + row) * DK + c] : 0.0f;
    }
    __syncthreads();
    for (int i = tid; i < 4096; i += 256) {
        int d = i >> 6, c = i & 63;
        Vth[((size_t)bh * DK + d) * SEQ + j0 + c] = __float2half_rn(ts[c][d]);
    }
}

// ============================================================================
// Prep kernels
// ============================================================================
__global__ void conv_b_kernel(const float4* __restrict__ q,
                              const float4* __restrict__ k,
                              const float4* __restrict__ v,
                              __half* __restrict__ Ah, int n4) {
    int i = blockIdx.x * blockDim.x + threadIdx.x;
    if (i >= n4) return;
    int z = blockIdx.y;
    const float4* in = (z == 0) ? q : (z == 1) ? k : v;
    __half2* hi = (__half2*)(Ah + (size_t)z * MT * D_MODEL);
    float4 vv = in[i];
    hi[2 * i]     = __floats2half2_rn(vv.x, vv.y);
    hi[2 * i + 1] = __floats2half2_rn(vv.z, vv.w);
}

__global__ void wt_split_b_kernel(const float* __restrict__ W0,
                                  const float* __restrict__ W1,
                                  const float* __restrict__ W2,
                                  const float* __restrict__ W3,
                                  __half* __restrict__ Wth) {
    __shared__ float ts[32][33];
    int z = blockIdx.z;
    const float* W = (z == 0) ? W0 : (z == 1) ? W1 : (z == 2) ? W2 : W3;
    __half* oh = Wth + (size_t)z * D_MODEL * D_MODEL;
    int n0 = blockIdx.x * 32, k0 = blockIdx.y * 32;
    ts[threadIdx.y][threadIdx.x] = W[(size_t)(k0 + threadIdx.y) * 512 + n0 + threadIdx.x];
    __syncthreads();
    int n = n0 + threadIdx.y, k = k0 + threadIdx.x;
    oh[(size_t)n * 512 + k] = __float2half_rn(ts[threadIdx.x][threadIdx.y]);
}

// ============================================================================
// HMMA GEMM (cp.async double-buffered), f16, f32-acc, single pass: Ah·Bh.
// BK=64: 8 k-chunks — half the barriers of BK=32, longer mma runs.
// z: 0=Q (pre-scaled by QSCALE, f16 head-split), 1=K (f16 head-split),
// 2=V (f32 head-split), 3=out proj (f32 row-major to d_out).
// ============================================================================
#define GRB    144     // smem row bytes (64 halves + 16B pad)
#define GTILE  (128 * GRB)      // 18432
#define GSTAGE (2 * GTILE)      // A + B
#define G_SMEM (2 * GSTAGE)     // 73728 — 2 CTAs/SM

__global__ __launch_bounds__(256, 2) void mm_gemm(
    const __half* __restrict__ Ahb, const __half* __restrict__ Wthb,
    const float* __restrict__ bq, const float* __restrict__ bk,
    const float* __restrict__ bv, const float* __restrict__ bo,
    __half* __restrict__ Qh, __half* __restrict__ Kh,
    float* __restrict__ Vf, float* __restrict__ dout, int zofs) {
    extern __shared__ __align__(16) char smg[];
    const int tid = threadIdx.x, wid = tid >> 5, lane = tid & 31;
    const int wm = wid >> 1, wn = wid & 1;
    const int gr = lane >> 2, gc = lane & 3;
    const int m0 = blockIdx.y * 128, n0 = blockIdx.x * 128;
    const int z = blockIdx.z + zofs;

    const __half* Ah = Ahb + (size_t)((z == 3) ? 0 : z) * MT * D_MODEL;
    const __half* Bh = Wthb + (size_t)z * D_MODEL * D_MODEL;
    const float* bias = (z == 0) ? bq : (z == 1) ? bk : (z == 2) ? bv : bo;

    const uint32_t sb = smem_to_u32(smg);
    const uint32_t rAh = (uint32_t)(wm * 32 + (lane & 15)) * GRB + (((lane >> 4) & 1) << 4);
    const uint32_t rBh = GTILE +
        (uint32_t)(wn * 64 + (lane & 7) + (((lane >> 4) & 1) << 3)) * GRB +
        (((lane >> 3) & 1) << 4);

    const int pr = tid >> 3, pj = tid & 7;   // 32 rows x 8 chunks per pass

    float c[2][8][4];
#pragma unroll
    for (int i = 0; i < 2; i++)
#pragma unroll
        for (int j = 0; j < 8; j++)
#pragma unroll
            for (int e = 0; e < 4; e++) c[i][j][e] = 0.0f;

    {
#pragma unroll
        for (int t = 0; t < 4; t++) {
            int r = pr + t * 32;
            uint32_t d = sb + (uint32_t)r * GRB + pj * 16;
            CP16(d, Ah + (size_t)(m0 + r) * 512 + pj * 8);
            CP16(d + GTILE, Bh + (size_t)(n0 + r) * 512 + pj * 8);
        }
        CP_COMMIT();
    }

    for (int kc = 0; kc < 8; kc++) {
        const uint32_t stg = sb + (uint32_t)(kc & 1) * GSTAGE;
        CP_WAIT0();
        __syncthreads();
        if (kc < 7) {
            const int k0 = (kc + 1) * 64;
            const uint32_t nstg = sb + (uint32_t)((kc + 1) & 1) * GSTAGE;
#pragma unroll
            for (int t = 0; t < 4; t++) {
                int r = pr + t * 32;
                uint32_t d = nstg + (uint32_t)r * GRB + pj * 16;
                CP16(d, Ah + (size_t)(m0 + r) * 512 + k0 + pj * 8);
                CP16(d + GTILE, Bh + (size_t)(n0 + r) * 512 + k0 + pj * 8);
            }
            CP_COMMIT();
        }

        const uint32_t aAh = stg + rAh, aBh = stg + rBh;
#pragma unroll
        for (int ks = 0; ks < 4; ks++) {
            uint32_t ah[2][4], bfr[4][4];
            ldsm4(ah[0], aAh + ks * 32);
            ldsm4(ah[1], aAh + 16 * GRB + ks * 32);
#pragma unroll
            for (int nt2 = 0; nt2 < 4; nt2++)
                ldsm4(bfr[nt2], aBh + nt2 * 16 * GRB + ks * 32);
#pragma unroll
            for (int nt2 = 0; nt2 < 4; nt2++)
#pragma unroll
                for (int q = 0; q < 2; q++)
#pragma unroll
                    for (int mt = 0; mt < 2; mt++)
                        mma_f32h(c[mt][nt2 * 2 + q], ah[mt], &bfr[nt2][q * 2]);
        }
    }

    // Epilogue
#pragma unroll
    for (int mt = 0; mt < 2; mt++) {
#pragma unroll
        for (int half_ = 0; half_ < 2; half_++) {
            int m = m0 + wm * 32 + mt * 16 + gr + half_ * 8;
            int bb = m >> 11, l = m & 2047;
#pragma unroll
            for (int nt = 0; nt < 8; nt++) {
                int n = n0 + wn * 64 + nt * 8 + 2 * gc;
                float v0 = c[mt][nt][half_ * 2 + 0] + bias[n];
                float v1 = c[mt][nt][half_ * 2 + 1] + bias[n + 1];
                if (z == 3) {
                    *(float2*)(dout + (size_t)m * 512 + n) = make_float2(v0, v1);
                } else if (z == 2) {
                    int h = n >> 6, d = n & 63;
                    *(float2*)(Vf + ((size_t)(bb * 8 + h) * SEQ + l) * DK + d) =
                        make_float2(v0, v1);
                } else {
                    if (z == 0) { v0 *= QSCALE; v1 *= QSCALE; }
                    int h = n >> 6, d = n & 63;
                    size_t o = ((size_t)(bb * 8 + h) * SEQ + l) * DK + d;
                    __half* oh = (z == 0) ? Qh : Kh;
                    *(__half2*)(oh + o) = __floats2half2_rn(v0, v1);
                }
            }
        }
    }
}

// ============================================================================
// HMMA flash attention over masked KV.
// K loaded DIRECTLY from the uncompacted projection via per-row index
// indirection (idx clamped to nk-1; clamped duplicates killed by tail mask).
// V from the compacted/transposed buffer. QK/PV single-pass f16, f32-acc.
// 2 CTAs/SM; Q in smem; log2-domain scores; magic exp2.
// ============================================================================
#define ARB   144                 // smem row bytes (72 halves)
#define ATILE (128 * ARB)         // one stage: K(64 rows) + V(64 rows)
#define QOFF  (2 * ATILE)         // Q region: 128 rows
#define A_SMEM (2 * ATILE + 128 * ARB)   // 55296 bytes

__global__ __launch_bounds__(256, 2) void mm_attn(
    const __half* __restrict__ Qh, const __half* __restrict__ Kh,
    const __half* __restrict__ Vh, const int* __restrict__ idx,
    const int* __restrict__ nkp, __half* __restrict__ OutH) {
    extern __shared__ __align__(16) char smA[];

    const int tid = threadIdx.x, wid = tid >> 5, lane = tid & 31;
    const int gr = lane >> 2, gc = lane & 3;
    const int q0 = blockIdx.x * 128;
    const int bh = blockIdx.y, b = bh >> 3, h = bh & 7;
    const int nk = nkp[b];
    const int niter = (nk + 63) >> 6;
    const int* idxb = idx + b * SEQ;

    const __half* Qhp = Qh + (size_t)bh * SEQ * DK;
    const __half* Khp = Kh + (size_t)bh * SEQ * DK;
    const __half* Vhp = Vh + (size_t)bh * DK * SEQ;

    const uint32_t sb = smem_to_u32(smA);
    const int pr = tid >> 3, pj = tid & 7;

    // ---- prefetch KV tile 0 into stage 0 (K rows 0-63 indirect, V 64-127)
    if (niter > 0) {
#pragma unroll
        for (int t = 0; t < 4; t++) {
            int r = pr + t * 32;
            uint32_t d = sb + (uint32_t)r * ARB + pj * 16;
            if (r < 64) {
                int jj = (r < nk) ? r : (nk - 1);
                int row = idxb[jj];
                CP16(d, Khp + (size_t)row * DK + pj * 8);
            } else {
                CP16(d, Vhp + (size_t)(r - 64) * SEQ + pj * 8);
            }
        }
        CP_COMMIT();
    }

    // ---- stage Q (persistent region)
#pragma unroll
    for (int t = 0; t < 2; t++) {
        int i = tid + t * 256;
        int r = i >> 2, j = i & 3;
        char* dst = smA + QOFF + (size_t)r * ARB + j * 32;
        const __half* src = Qhp + (size_t)(q0 + r) * DK + j * 16;
        *(uint4*)dst = *(const uint4*)src;
        *(uint4*)(dst + 16) = *(const uint4*)(src + 8);
    }
    CP_WAIT0();
    __syncthreads();

    const uint32_t aQb = sb + QOFF +
        (uint32_t)(wid * 16 + (lane & 15)) * ARB + (((lane >> 4) & 1) << 4);
    const uint32_t bro = (uint32_t)((lane & 7) + (((lane >> 4) & 1) << 3)) * ARB +
                         (((lane >> 3) & 1) << 4);

    float m0_ = -1e30f, m1_ = -1e30f, l0_ = 0.0f, l1_ = 0.0f;
    float o[8][4];
#pragma unroll
    for (int j = 0; j < 8; j++)
#pragma unroll
        for (int e = 0; e < 4; e++) o[j][e] = 0.0f;

    for (int it = 0; it < niter; it++) {
        const int cur = it & 1;
        const uint32_t stg = sb + (uint32_t)cur * ATILE;
        const int kt = it * 64;

        if (it + 1 < niter) {
            const int ktn = kt + 64;
            const uint32_t nstg = sb + (uint32_t)(1 - cur) * ATILE;
#pragma unroll
            for (int t = 0; t < 4; t++) {
                int r = pr + t * 32;
                uint32_t d = nstg + (uint32_t)r * ARB + pj * 16;
                if (r < 64) {
                    int jj = ktn + r;
                    jj = (jj < nk) ? jj : (nk - 1);
                    int row = idxb[jj];
                    CP16(d, Khp + (size_t)row * DK + pj * 8);
                } else {
                    CP16(d, Vhp + (size_t)(r - 64) * SEQ + ktn + pj * 8);
                }
            }
            CP_COMMIT();
        }

        // ---- S = Qh·Kh (f32 acc; log2 units)
        float s[8][4];
#pragma unroll
        for (int j = 0; j < 8; j++)
#pragma unroll
            for (int e = 0; e < 4; e++) s[j][e] = 0.0f;
        const uint32_t aKh = stg + bro;
#pragma unroll
        for (int ks = 0; ks < 4; ks++) {
            uint32_t qhf[4], kf[4][4];
            ldsm4(qhf, aQb + ks * 32);
#pragma unroll
            for (int nt2 = 0; nt2 < 4; nt2++)
                ldsm4(kf[nt2], aKh + nt2 * 16 * ARB + ks * 32);
#pragma unroll
            for (int nt2 = 0; nt2 < 4; nt2++)
#pragma unroll
                for (int q = 0; q < 2; q++)
                    mma_f32h(s[nt2 * 2 + q], qhf, &kf[nt2][q * 2]);
        }

        // ---- tail-tile masking (uniform branch; kills clamped duplicates)
        if (kt + 64 > nk) {
#pragma unroll
            for (int nt = 0; nt < 8; nt++) {
                int cb = kt + nt * 8 + 2 * gc;
                if (cb >= nk)     { s[nt][0] = -3.0e38f; s[nt][2] = -3.0e38f; }
                if (cb + 1 >= nk) { s[nt][1] = -3.0e38f; s[nt][3] = -3.0e38f; }
            }
        }

        // ---- row max (log2 domain)
        float mx0 = -3.0e38f, mx1 = -3.0e38f;
#pragma unroll
        for (int nt = 0; nt < 8; nt++) {
            mx0 = fmaxf(mx0, fmaxf(s[nt][0], s[nt][1]));
            mx1 = fmaxf(mx1, fmaxf(s[nt][2], s[nt][3]));
        }
        mx0 = fmaxf(mx0, __shfl_xor_sync(0xffffffffu, mx0, 1));
        mx0 = fmaxf(mx0, __shfl_xor_sync(0xffffffffu, mx0, 2));
        mx1 = fmaxf(mx1, __shfl_xor_sync(0xffffffffu, mx1, 1));
        mx1 = fmaxf(mx1, __shfl_xor_sync(0xffffffffu, mx1, 2));
        float mn0 = fmaxf(m0_, mx0), mn1 = fmaxf(m1_, mx1);
        float al0 = fexp2m(m0_ - mn0), al1 = fexp2m(m1_ - mn1);
        m0_ = mn0;
        m1_ = mn1;

        // ---- exp + sums + pack P into mma A-fragments
        uint32_t pa_h[4][4];
        float sm0 = 0.0f, sm1 = 0.0f;
#pragma unroll
        for (int nt = 0; nt < 8; nt++) {
            float p0 = fexp2m(s[nt][0] - mn0);
            float p1 = fexp2m(s[nt][1] - mn0);
            float p2 = fexp2m(s[nt][2] - mn1);
            float p3 = fexp2m(s[nt][3] - mn1);
            sm0 += p0 + p1;
            sm1 += p2 + p3;
            int kp = nt >> 1, q = nt & 1;
            __half2 hb01 = __floats2half2_rn(p0, p1);
            __half2 hb23 = __floats2half2_rn(p2, p3);
            pa_h[kp][q * 2 + 0] = *(uint32_t*)&hb01;
            pa_h[kp][q * 2 + 1] = *(uint32_t*)&hb23;
        }
        sm0 += __shfl_xor_sync(0xffffffffu, sm0, 1);
        sm0 += __shfl_xor_sync(0xffffffffu, sm0, 2);
        sm1 += __shfl_xor_sync(0xffffffffu, sm1, 1);
        sm1 += __shfl_xor_sync(0xffffffffu, sm1, 2);
        l0_ = l0_ * al0 + sm0;
        l1_ = l1_ * al1 + sm1;

#pragma unroll
        for (int j = 0; j < 8; j++) {
            o[j][0] *= al0;
            o[j][1] *= al0;
            o[j][2] *= al1;
            o[j][3] *= al1;
        }

        // ---- O += Ph·Vh (f32 acc)
        const uint32_t aVh = stg + 64 * ARB + bro;
#pragma unroll
        for (int kp = 0; kp < 4; kp++) {
            uint32_t vf[4][4];
#pragma unroll
            for (int nt2 = 0; nt2 < 4; nt2++)
                ldsm4(vf[nt2], aVh + nt2 * 16 * ARB + kp * 32);
#pragma unroll
            for (int nt2 = 0; nt2 < 4; nt2++)
#pragma unroll
                for (int q = 0; q < 2; q++)
                    mma_f32h(o[nt2 * 2 + q], pa_h[kp], &vf[nt2][q * 2]);
        }

        if (it + 1 < niter) {
            CP_WAIT0();
            __syncthreads();
        }
    }

    // ---- normalize + store f16 at (B, L, H*64) for out-proj
    float inv0 = (l0_ > 0.0f) ? 1.0f / l0_ : 0.0f;
    float inv1 = (l1_ > 0.0f) ? 1.0f / l1_ : 0.0f;
    int r0 = q0 + wid * 16 + gr, r1 = r0 + 8;
    size_t base0 = (size_t)(b * SEQ + r0) * D_MODEL + h * DK;
    size_t base1 = (size_t)(b * SEQ + r1) * D_MODEL + h * DK;
#pragma unroll
    for (int nt = 0; nt < 8; nt++) {
        int cl = nt * 8 + 2 * gc;
        *(__half2*)(OutH + base0 + cl) =
            __floats2half2_rn(o[nt][0] * inv0, o[nt][1] * inv0);
        *(__half2*)(OutH + base1 + cl) =
            __floats2half2_rn(o[nt][2] * inv1, o[nt][3] * inv1);
    }
}

// ============================================================================
// Launch: 7 kernels total
// ============================================================================
extern "C" void kernel_launch(void* const* d_in, const int* in_sizes, int n_in,
                              void* d_out, int out_size) {
    const float* query = (const float*)d_in[0];
    const float* key   = (const float*)d_in[1];
    const float* value = (const float*)d_in[2];
    const int*   mask  = (const int*)d_in[3];
    const float* Wq = (const float*)d_in[4];
    const float* bq = (const float*)d_in[5];
    const float* Wk = (const float*)d_in[6];
    const float* bk = (const float*)d_in[7];
    const float* Wv = (const float*)d_in[8];
    const float* bv = (const float*)d_in[9];
    const float* Wo = (const float*)d_in[10];
    const float* bo = (const float*)d_in[11];

    __half *Ah, *Wth, *Qh, *Kh, *Vth;
    float *Vf;
    int *idx, *nk;
    cudaGetSymbolAddress((void**)&Ah, g_Ah);
    cudaGetSymbolAddress((void**)&Wth, g_Wth);
    cudaGetSymbolAddress((void**)&Qh, g_Qh);
    cudaGetSymbolAddress((void**)&Kh, g_Kh);
    cudaGetSymbolAddress((void**)&Vf, g_Vf);
    cudaGetSymbolAddress((void**)&Vth, g_Vth);
    cudaGetSymbolAddress((void**)&idx, g_idx);
    cudaGetSymbolAddress((void**)&nk, g_nk);

    cudaFuncSetAttribute(mm_gemm, cudaFuncAttributeMaxDynamicSharedMemorySize,
                         G_SMEM);
    cudaFuncSetAttribute(mm_attn, cudaFuncAttributeMaxDynamicSharedMemorySize,
                         A_SMEM);

    const int N4 = MT * D_MODEL / 4;

    mask_scan_kernel<<<BATCH, 1024>>>(mask, idx, nk);
    wt_split_b_kernel<<<dim3(16, 16, 4), dim3(32, 32)>>>(Wq, Wk, Wv, Wo, Wth);
    conv_b_kernel<<<dim3(N4 / 256, 3), 256>>>((const float4*)query,
                                              (const float4*)key,
                                              (const float4*)value, Ah, N4);
    mm_gemm<<<dim3(4, 64, 3), 256, G_SMEM>>>(Ah, Wth, bq, bk, bv, bo,
                                             Qh, Kh, Vf, nullptr, 0);
    v_gather_kernel<<<dim3(SEQ / 64, BH), 256>>>(Vf, idx, nk, Vth);
    mm_attn<<<dim3(SEQ / 128, BH), 256, A_SMEM>>>(Qh, Kh, Vth, idx, nk, Ah);
    mm_gemm<<<dim3(4, 64, 1), 256, G_SMEM>>>(Ah, Wth, bq, bk, bv, bo,
                                             nullptr, nullptr, nullptr,
                                             (float*)d_out, 3);
}

// round 16
// speedup vs baseline: 2.3076x; 1.0286x over previous
#include <cuda_runtime.h>
#include <cuda_fp16.h>
#include <cstdint>

#define NUM_HEADS 8
#define D_MODEL   512
#define DK        64
#define SEQ       2048
#define BATCH     4
#define MT        (BATCH * SEQ)        // 8192
#define BH        (BATCH * NUM_HEADS)  // 32

// ============================================================================
// Scratch (device globals — no allocation allowed)
// ============================================================================
__device__ __align__(16) __half g_Ah[3 * MT * D_MODEL];
__device__ __align__(16) __half g_Wth[4 * D_MODEL * D_MODEL];
__device__ __align__(16) __half g_Qh[BH * SEQ * DK];
__device__ __align__(16) __half g_Kh[BH * SEQ * DK];
__device__ __align__(16) __half g_Vh[BH * SEQ * DK];
__device__ int g_idx[BATCH * SEQ];
__device__ int g_nk[BATCH];

// 0.125 (1/sqrt(d_k)) * log2(e): folded into Q projection so S is in log2 units
#define QSCALE 0.18033688011117128f

// ============================================================================
// PTX primitives (all legal at compute_103 baseline)
// ============================================================================
__device__ __forceinline__ uint32_t smem_to_u32(const void* p) {
    uint32_t a;
    asm("{ .reg .u64 t; cvta.to.shared.u64 t, %1; cvt.u32.u64 %0, t; }"
        : "=r"(a) : "l"(p));
    return a;
}

__device__ __forceinline__ void ldsm4(uint32_t* r, uint32_t addr) {
    asm volatile("ldmatrix.sync.aligned.m8n8.x4.shared.b16 {%0,%1,%2,%3}, [%4];"
                 : "=r"(r[0]), "=r"(r[1]), "=r"(r[2]), "=r"(r[3]) : "r"(addr));
}

// transposing variant — B operand directly from row-major [k][n] storage
__device__ __forceinline__ void ldsm4t(uint32_t* r, uint32_t addr) {
    asm volatile("ldmatrix.sync.aligned.m8n8.x4.trans.shared.b16 {%0,%1,%2,%3}, [%4];"
                 : "=r"(r[0]), "=r"(r[1]), "=r"(r[2]), "=r"(r[3]) : "r"(addr));
}

// f16 inputs, f32 accumulate
__device__ __forceinline__ void mma_f32h(float* c, const uint32_t* a,
                                         const uint32_t* b) {
    asm volatile(
        "mma.sync.aligned.m16n8k16.row.col.f32.f16.f16.f32 "
        "{%0,%1,%2,%3}, {%4,%5,%6,%7}, {%8,%9}, {%0,%1,%2,%3};"
        : "+f"(c[0]), "+f"(c[1]), "+f"(c[2]), "+f"(c[3])
        : "r"(a[0]), "r"(a[1]), "r"(a[2]), "r"(a[3]), "r"(b[0]), "r"(b[1]));
}

#define CP16(dst, src) \
    asm volatile("cp.async.cg.shared.global [%0], [%1], 16;" \
                 :: "r"(dst), "l"(src) : "memory")
#define CP_COMMIT() asm volatile("cp.async.commit_group;" ::: "memory")
#define CP_WAIT0()  asm volatile("cp.async.wait_group 0;" ::: "memory")

// exp2 via magic-constant round + degree-4 poly on [-0.5, 0.5]; t <= 0.
__device__ __forceinline__ float fexp2m(float t) {
    t = fmaxf(t, -126.0f);
    float z = t + 12582912.0f;
    float f = t - (z - 12582912.0f);
    float p = fmaf(f, 0.0096181291f, 0.0555041087f);
    p = fmaf(p, f, 0.2402265069f);
    p = fmaf(p, f, 0.6931471806f);
    p = fmaf(p, f, 1.0f);
    uint32_t sb = (uint32_t)((__float_as_int(z) + 127) << 23);
    return __int_as_float(sb) * p;
}

// ============================================================================
// Mask prefix scan
// ============================================================================
__global__ __launch_bounds__(1024) void mask_scan_kernel(
    const int* __restrict__ mask, int* __restrict__ idx, int* __restrict__ nk) {
    const int b = blockIdx.x, tid = threadIdx.x;
    const int lane = tid & 31, w = tid >> 5;
    const int* mp = mask + b * SEQ;
    int e0 = (mp[2 * tid] != 0), e1 = (mp[2 * tid + 1] != 0);
    int tsum = e0 + e1;
    int v = tsum;
#pragma unroll
    for (int o = 1; o < 32; o <<= 1) {
        int u = __shfl_up_sync(0xffffffffu, v, o);
        if (lane >= o) v += u;
    }
    __shared__ int ws[32];
    if (lane == 31) ws[w] = v;
    __syncthreads();
    if (w == 0) {
        int x = ws[lane];
#pragma unroll
        for (int o = 1; o < 32; o <<= 1) {
            int u = __shfl_up_sync(0xffffffffu, x, o);
            if (lane >= o) x += u;
        }
        ws[lane] = x;
    }
    __syncthreads();
    int base = ((w > 0) ? ws[w - 1] : 0) + (v - tsum);
    if (e0) idx[b * SEQ + base] = 2 * tid;
    if (e1) idx[b * SEQ + base + e0] = 2 * tid + 1;
    if (tid == 0) nk[b] = ws[31];
}

// ============================================================================
// Prep kernels
// ============================================================================
__global__ void conv_b_kernel(const float4* __restrict__ q,
                              const float4* __restrict__ k,
                              const float4* __restrict__ v,
                              __half* __restrict__ Ah, int n4) {
    int i = blockIdx.x * blockDim.x + threadIdx.x;
    if (i >= n4) return;
    int z = blockIdx.y;
    const float4* in = (z == 0) ? q : (z == 1) ? k : v;
    __half2* hi = (__half2*)(Ah + (size_t)z * MT * D_MODEL);
    float4 vv = in[i];
    hi[2 * i]     = __floats2half2_rn(vv.x, vv.y);
    hi[2 * i + 1] = __floats2half2_rn(vv.z, vv.w);
}

__global__ void wt_split_b_kernel(const float* __restrict__ W0,
                                  const float* __restrict__ W1,
                                  const float* __restrict__ W2,
                                  const float* __restrict__ W3,
                                  __half* __restrict__ Wth) {
    __shared__ float ts[32][33];
    int z = blockIdx.z;
    const float* W = (z == 0) ? W0 : (z == 1) ? W1 : (z == 2) ? W2 : W3;
    __half* oh = Wth + (size_t)z * D_MODEL * D_MODEL;
    int n0 = blockIdx.x * 32, k0 = blockIdx.y * 32;
    ts[threadIdx.y][threadIdx.x] = W[(size_t)(k0 + threadIdx.y) * 512 + n0 + threadIdx.x];
    __syncthreads();
    int n = n0 + threadIdx.y, k = k0 + threadIdx.x;
    oh[(size_t)n * 512 + k] = __float2half_rn(ts[threadIdx.x][threadIdx.y]);
}

// ============================================================================
// HMMA GEMM (cp.async double-buffered), f16, f32-acc, single pass: Ah·Bh.
// BK=64. z: 0=Q (QSCALE, f16 head-split), 1=K (f16 head-split),
// 2=V (f16 head-split), 3=out proj (f32 row-major to d_out).
// ============================================================================
#define GRB    144     // smem row bytes (64 halves + 16B pad)
#define GTILE  (128 * GRB)      // 18432
#define GSTAGE (2 * GTILE)      // A + B
#define G_SMEM (2 * GSTAGE)     // 73728 — 2 CTAs/SM

__global__ __launch_bounds__(256, 2) void mm_gemm(
    const __half* __restrict__ Ahb, const __half* __restrict__ Wthb,
    const float* __restrict__ bq, const float* __restrict__ bk,
    const float* __restrict__ bv, const float* __restrict__ bo,
    __half* __restrict__ Qh, __half* __restrict__ Kh, __half* __restrict__ Vh,
    float* __restrict__ dout, int zofs) {
    extern __shared__ __align__(16) char smg[];
    const int tid = threadIdx.x, wid = tid >> 5, lane = tid & 31;
    const int wm = wid >> 1, wn = wid & 1;
    const int gr = lane >> 2, gc = lane & 3;
    const int m0 = blockIdx.y * 128, n0 = blockIdx.x * 128;
    const int z = blockIdx.z + zofs;

    const __half* Ah = Ahb + (size_t)((z == 3) ? 0 : z) * MT * D_MODEL;
    const __half* Bh = Wthb + (size_t)z * D_MODEL * D_MODEL;
    const float* bias = (z == 0) ? bq : (z == 1) ? bk : (z == 2) ? bv : bo;

    const uint32_t sb = smem_to_u32(smg);
    const uint32_t rAh = (uint32_t)(wm * 32 + (lane & 15)) * GRB + (((lane >> 4) & 1) << 4);
    const uint32_t rBh = GTILE +
        (uint32_t)(wn * 64 + (lane & 7) + (((lane >> 4) & 1) << 3)) * GRB +
        (((lane >> 3) & 1) << 4);

    const int pr = tid >> 3, pj = tid & 7;

    float c[2][8][4];
#pragma unroll
    for (int i = 0; i < 2; i++)
#pragma unroll
        for (int j = 0; j < 8; j++)
#pragma unroll
            for (int e = 0; e < 4; e++) c[i][j][e] = 0.0f;

    {
#pragma unroll
        for (int t = 0; t < 4; t++) {
            int r = pr + t * 32;
            uint32_t d = sb + (uint32_t)r * GRB + pj * 16;
            CP16(d, Ah + (size_t)(m0 + r) * 512 + pj * 8);
            CP16(d + GTILE, Bh + (size_t)(n0 + r) * 512 + pj * 8);
        }
        CP_COMMIT();
    }

    for (int kc = 0; kc < 8; kc++) {
        const uint32_t stg = sb + (uint32_t)(kc & 1) * GSTAGE;
        CP_WAIT0();
        __syncthreads();
        if (kc < 7) {
            const int k0 = (kc + 1) * 64;
            const uint32_t nstg = sb + (uint32_t)((kc + 1) & 1) * GSTAGE;
#pragma unroll
            for (int t = 0; t < 4; t++) {
                int r = pr + t * 32;
                uint32_t d = nstg + (uint32_t)r * GRB + pj * 16;
                CP16(d, Ah + (size_t)(m0 + r) * 512 + k0 + pj * 8);
                CP16(d + GTILE, Bh + (size_t)(n0 + r) * 512 + k0 + pj * 8);
            }
            CP_COMMIT();
        }

        const uint32_t aAh = stg + rAh, aBh = stg + rBh;
#pragma unroll
        for (int ks = 0; ks < 4; ks++) {
            uint32_t ah[2][4], bfr[4][4];
            ldsm4(ah[0], aAh + ks * 32);
            ldsm4(ah[1], aAh + 16 * GRB + ks * 32);
#pragma unroll
            for (int nt2 = 0; nt2 < 4; nt2++)
                ldsm4(bfr[nt2], aBh + nt2 * 16 * GRB + ks * 32);
#pragma unroll
            for (int nt2 = 0; nt2 < 4; nt2++)
#pragma unroll
                for (int q = 0; q < 2; q++)
#pragma unroll
                    for (int mt = 0; mt < 2; mt++)
                        mma_f32h(c[mt][nt2 * 2 + q], ah[mt], &bfr[nt2][q * 2]);
        }
    }

    // Epilogue
#pragma unroll
    for (int mt = 0; mt < 2; mt++) {
#pragma unroll
        for (int half_ = 0; half_ < 2; half_++) {
            int m = m0 + wm * 32 + mt * 16 + gr + half_ * 8;
            int bb = m >> 11, l = m & 2047;
#pragma unroll
            for (int nt = 0; nt < 8; nt++) {
                int n = n0 + wn * 64 + nt * 8 + 2 * gc;
                float v0 = c[mt][nt][half_ * 2 + 0] + bias[n];
                float v1 = c[mt][nt][half_ * 2 + 1] + bias[n + 1];
                if (z == 3) {
                    *(float2*)(dout + (size_t)m * 512 + n) = make_float2(v0, v1);
                } else {
                    if (z == 0) { v0 *= QSCALE; v1 *= QSCALE; }
                    int h = n >> 6, d = n & 63;
                    size_t o = ((size_t)(bb * 8 + h) * SEQ + l) * DK + d;
                    __half* oh = (z == 0) ? Qh : (z == 1) ? Kh : Vh;
                    *(__half2*)(oh + o) = __floats2half2_rn(v0, v1);
                }
            }
        }
    }
}

// ============================================================================
// HMMA flash attention. K AND V both loaded directly from uncompacted
// projections via per-row index indirection (clamped; duplicates killed by
// tail mask / zero P). V transposed in-register via ldmatrix.trans.
// Per-kp interleave: exp+pack of chunk k overlaps PV mma of the same chunk.
// QK/PV single-pass f16, f32-acc. 2 CTAs/SM; Q in smem; log2-domain scores.
// ============================================================================
#define ARB   144                 // smem row bytes (72 halves)
#define ATILE (128 * ARB)         // one stage: K(64 rows) + V(64 rows), [l][d]
#define QOFF  (2 * ATILE)         // Q region: 128 rows
#define A_SMEM (2 * ATILE + 128 * ARB)   // 55296 bytes

__global__ __launch_bounds__(256, 2) void mm_attn(
    const __half* __restrict__ Qh, const __half* __restrict__ Kh,
    const __half* __restrict__ Vh, const int* __restrict__ idx,
    const int* __restrict__ nkp, __half* __restrict__ OutH) {
    extern __shared__ __align__(16) char smA[];

    const int tid = threadIdx.x, wid = tid >> 5, lane = tid & 31;
    const int gr = lane >> 2, gc = lane & 3;
    const int q0 = blockIdx.x * 128;
    const int bh = blockIdx.y, b = bh >> 3, h = bh & 7;
    const int nk = nkp[b];
    const int niter = (nk + 63) >> 6;
    const int* idxb = idx + b * SEQ;

    const __half* Qhp = Qh + (size_t)bh * SEQ * DK;
    const __half* Khp = Kh + (size_t)bh * SEQ * DK;
    const __half* Vhp = Vh + (size_t)bh * SEQ * DK;

    const uint32_t sb = smem_to_u32(smA);
    const int pr = tid >> 3, pj = tid & 7;

    // ---- prefetch KV tile 0 into stage 0 (K rows 0-63, V rows 64-127; both
    //      row-indirect through idx, rows stored [l][d])
    if (niter > 0) {
#pragma unroll
        for (int t = 0; t < 4; t++) {
            int r = pr + t * 32;
            uint32_t d = sb + (uint32_t)r * ARB + pj * 16;
            int rl = (r < 64) ? r : (r - 64);
            int jj = (rl < nk) ? rl : (nk - 1);
            int row = idxb[jj];
            const __half* src = (r < 64) ? Khp : Vhp;
            CP16(d, src + (size_t)row * DK + pj * 8);
        }
        CP_COMMIT();
    }

    // ---- stage Q (persistent region)
#pragma unroll
    for (int t = 0; t < 2; t++) {
        int i = tid + t * 256;
        int r = i >> 2, j = i & 3;
        char* dst = smA + QOFF + (size_t)r * ARB + j * 32;
        const __half* src = Qhp + (size_t)(q0 + r) * DK + j * 16;
        *(uint4*)dst = *(const uint4*)src;
        *(uint4*)(dst + 16) = *(const uint4*)(src + 8);
    }
    CP_WAIT0();
    __syncthreads();

    const uint32_t aQb = sb + QOFF +
        (uint32_t)(wid * 16 + (lane & 15)) * ARB + (((lane >> 4) & 1) << 4);
    // K (B operand, non-trans; storage [n=kv][k=dk])
    const uint32_t bro = (uint32_t)((lane & 7) + (((lane >> 4) & 1) << 3)) * ARB +
                         (((lane >> 3) & 1) << 4);
    // V (B operand, trans; storage [k=kv][n=dk])
    const uint32_t vro = (uint32_t)((lane & 7) + (((lane >> 3) & 1) << 3)) * ARB +
                         (((lane >> 4) & 1) << 4);

    float m0_ = -1e30f, m1_ = -1e30f, l0_ = 0.0f, l1_ = 0.0f;
    float o[8][4];
#pragma unroll
    for (int j = 0; j < 8; j++)
#pragma unroll
        for (int e = 0; e < 4; e++) o[j][e] = 0.0f;

    for (int it = 0; it < niter; it++) {
        const int cur = it & 1;
        const uint32_t stg = sb + (uint32_t)cur * ATILE;
        const int kt = it * 64;

        if (it + 1 < niter) {
            const int ktn = kt + 64;
            const uint32_t nstg = sb + (uint32_t)(1 - cur) * ATILE;
#pragma unroll
            for (int t = 0; t < 4; t++) {
                int r = pr + t * 32;
                uint32_t d = nstg + (uint32_t)r * ARB + pj * 16;
                int rl = (r < 64) ? r : (r - 64);
                int jj = ktn + rl;
                jj = (jj < nk) ? jj : (nk - 1);
                int row = idxb[jj];
                const __half* src = (r < 64) ? Khp : Vhp;
                CP16(d, src + (size_t)row * DK + pj * 8);
            }
            CP_COMMIT();
        }

        // ---- S = Qh·Kh (f32 acc; log2 units)
        float s[8][4];
#pragma unroll
        for (int j = 0; j < 8; j++)
#pragma unroll
            for (int e = 0; e < 4; e++) s[j][e] = 0.0f;
        const uint32_t aKh = stg + bro;
#pragma unroll
        for (int ks = 0; ks < 4; ks++) {
            uint32_t qhf[4], kf[4][4];
            ldsm4(qhf, aQb + ks * 32);
#pragma unroll
            for (int nt2 = 0; nt2 < 4; nt2++)
                ldsm4(kf[nt2], aKh + nt2 * 16 * ARB + ks * 32);
#pragma unroll
            for (int nt2 = 0; nt2 < 4; nt2++)
#pragma unroll
                for (int q = 0; q < 2; q++)
                    mma_f32h(s[nt2 * 2 + q], qhf, &kf[nt2][q * 2]);
        }

        // ---- tail-tile masking (uniform branch; kills clamped duplicates)
        if (kt + 64 > nk) {
#pragma unroll
            for (int nt = 0; nt < 8; nt++) {
                int cb = kt + nt * 8 + 2 * gc;
                if (cb >= nk)     { s[nt][0] = -3.0e38f; s[nt][2] = -3.0e38f; }
                if (cb + 1 >= nk) { s[nt][1] = -3.0e38f; s[nt][3] = -3.0e38f; }
            }
        }

        // ---- row max (log2 domain)
        float mx0 = -3.0e38f, mx1 = -3.0e38f;
#pragma unroll
        for (int nt = 0; nt < 8; nt++) {
            mx0 = fmaxf(mx0, fmaxf(s[nt][0], s[nt][1]));
            mx1 = fmaxf(mx1, fmaxf(s[nt][2], s[nt][3]));
        }
        mx0 = fmaxf(mx0, __shfl_xor_sync(0xffffffffu, mx0, 1));
        mx0 = fmaxf(mx0, __shfl_xor_sync(0xffffffffu, mx0, 2));
        mx1 = fmaxf(mx1, __shfl_xor_sync(0xffffffffu, mx1, 1));
        mx1 = fmaxf(mx1, __shfl_xor_sync(0xffffffffu, mx1, 2));
        float mn0 = fmaxf(m0_, mx0), mn1 = fmaxf(m1_, mx1);
        float al0 = fexp2m(m0_ - mn0), al1 = fexp2m(m1_ - mn1);
        m0_ = mn0;
        m1_ = mn1;

        // rescale O before accumulating this tile
#pragma unroll
        for (int j = 0; j < 8; j++) {
            o[j][0] *= al0;
            o[j][1] *= al0;
            o[j][2] *= al1;
            o[j][3] *= al1;
        }

        // ---- per-kp interleave: exp+pack(8) -> trans-ldsm V -> 8 PV mmas
        const uint32_t aVh = stg + 64 * ARB + vro;
        float sm0 = 0.0f, sm1 = 0.0f;
#pragma unroll
        for (int kp = 0; kp < 4; kp++) {
            uint32_t pa[4];
#pragma unroll
            for (int q = 0; q < 2; q++) {
                int nt = kp * 2 + q;
                float p0 = fexp2m(s[nt][0] - mn0);
                float p1 = fexp2m(s[nt][1] - mn0);
                float p2 = fexp2m(s[nt][2] - mn1);
                float p3 = fexp2m(s[nt][3] - mn1);
                sm0 += p0 + p1;
                sm1 += p2 + p3;
                __half2 hb01 = __floats2half2_rn(p0, p1);
                __half2 hb23 = __floats2half2_rn(p2, p3);
                pa[q * 2 + 0] = *(uint32_t*)&hb01;
                pa[q * 2 + 1] = *(uint32_t*)&hb23;
            }
            uint32_t vf[4][4];
#pragma unroll
            for (int nt2 = 0; nt2 < 4; nt2++)
                ldsm4t(vf[nt2], aVh + kp * 16 * ARB + nt2 * 32);
#pragma unroll
            for (int nt2 = 0; nt2 < 4; nt2++)
#pragma unroll
                for (int q = 0; q < 2; q++)
                    mma_f32h(o[nt2 * 2 + q], pa, &vf[nt2][q * 2]);
        }
        sm0 += __shfl_xor_sync(0xffffffffu, sm0, 1);
        sm0 += __shfl_xor_sync(0xffffffffu, sm0, 2);
        sm1 += __shfl_xor_sync(0xffffffffu, sm1, 1);
        sm1 += __shfl_xor_sync(0xffffffffu, sm1, 2);
        l0_ = l0_ * al0 + sm0;
        l1_ = l1_ * al1 + sm1;

        if (it + 1 < niter) {
            CP_WAIT0();
            __syncthreads();
        }
    }

    // ---- normalize + store f16 at (B, L, H*64) for out-proj
    float inv0 = (l0_ > 0.0f) ? 1.0f / l0_ : 0.0f;
    float inv1 = (l1_ > 0.0f) ? 1.0f / l1_ : 0.0f;
    int r0 = q0 + wid * 16 + gr, r1 = r0 + 8;
    size_t base0 = (size_t)(b * SEQ + r0) * D_MODEL + h * DK;
    size_t base1 = (size_t)(b * SEQ + r1) * D_MODEL + h * DK;
#pragma unroll
    for (int nt = 0; nt < 8; nt++) {
        int cl = nt * 8 + 2 * gc;
        *(__half2*)(OutH + base0 + cl) =
            __floats2half2_rn(o[nt][0] * inv0, o[nt][1] * inv0);
        *(__half2*)(OutH + base1 + cl) =
            __floats2half2_rn(o[nt][2] * inv1, o[nt][3] * inv1);
    }
}

// ============================================================================
// Launch: 6 kernels total
// ============================================================================
extern "C" void kernel_launch(void* const* d_in, const int* in_sizes, int n_in,
                              void* d_out, int out_size) {
    const float* query = (const float*)d_in[0];
    const float* key   = (const float*)d_in[1];
    const float* value = (const float*)d_in[2];
    const int*   mask  = (const int*)d_in[3];
    const float* Wq = (const float*)d_in[4];
    const float* bq = (const float*)d_in[5];
    const float* Wk = (const float*)d_in[6];
    const float* bk = (const float*)d_in[7];
    const float* Wv = (const float*)d_in[8];
    const float* bv = (const float*)d_in[9];
    const float* Wo = (const float*)d_in[10];
    const float* bo = (const float*)d_in[11];

    __half *Ah, *Wth, *Qh, *Kh, *Vh;
    int *idx, *nk;
    cudaGetSymbolAddress((void**)&Ah, g_Ah);
    cudaGetSymbolAddress((void**)&Wth, g_Wth);
    cudaGetSymbolAddress((void**)&Qh, g_Qh);
    cudaGetSymbolAddress((void**)&Kh, g_Kh);
    cudaGetSymbolAddress((void**)&Vh, g_Vh);
    cudaGetSymbolAddress((void**)&idx, g_idx);
    cudaGetSymbolAddress((void**)&nk, g_nk);

    cudaFuncSetAttribute(mm_gemm, cudaFuncAttributeMaxDynamicSharedMemorySize,
                         G_SMEM);
    cudaFuncSetAttribute(mm_attn, cudaFuncAttributeMaxDynamicSharedMemorySize,
                         A_SMEM);

    const int N4 = MT * D_MODEL / 4;

    mask_scan_kernel<<<BATCH, 1024>>>(mask, idx, nk);
    wt_split_b_kernel<<<dim3(16, 16, 4), dim3(32, 32)>>>(Wq, Wk, Wv, Wo, Wth);
    conv_b_kernel<<<dim3(N4 / 256, 3), 256>>>((const float4*)query,
                                              (const float4*)key,
                                              (const float4*)value, Ah, N4);
    mm_gemm<<<dim3(4, 64, 3), 256, G_SMEM>>>(Ah, Wth, bq, bk, bv, bo,
                                             Qh, Kh, Vh, nullptr, 0);
    mm_attn<<<dim3(SEQ / 128, BH), 256, A_SMEM>>>(Qh, Kh, Vh, idx, nk, Ah);
    mm_gemm<<<dim3(4, 64, 1), 256, G_SMEM>>>(Ah, Wth, bq, bk, bv, bo,
                                             nullptr, nullptr, nullptr,
                                             (float*)d_out, 3);
}